// round 10
// baseline (speedup 1.0000x reference)
#include <cuda_runtime.h>
#include <cuda_fp16.h>
#include <math.h>
#include <stdint.h>

#define D_MODEL 1024
#define NHEADS  16
#define DKH     64
#define D_FF    4096
#define BATCH   2
#define SEQ     2048
#define NROWS   (BATCH*SEQ)
#define LN_EPS  1e-6f

#define SWZ128(x) ((x) ^ (((x) >> 3) & 0x70))

// ================= PTX helpers ============================================
__device__ __forceinline__ uint32_t smem_u32(const void* p) {
    uint32_t a;
    asm("{ .reg .u64 t; cvta.to.shared.u64 t, %1; cvt.u32.u64 %0, t; }" : "=r"(a) : "l"(p));
    return a;
}
__device__ __forceinline__ void ldsm_x4(uint32_t& r0, uint32_t& r1, uint32_t& r2, uint32_t& r3, uint32_t addr) {
    asm volatile("ldmatrix.sync.aligned.m8n8.x4.shared.b16 {%0,%1,%2,%3}, [%4];"
                 : "=r"(r0), "=r"(r1), "=r"(r2), "=r"(r3) : "r"(addr));
}
__device__ __forceinline__ void ldsm_x4_t(uint32_t& r0, uint32_t& r1, uint32_t& r2, uint32_t& r3, uint32_t addr) {
    asm volatile("ldmatrix.sync.aligned.m8n8.x4.trans.shared.b16 {%0,%1,%2,%3}, [%4];"
                 : "=r"(r0), "=r"(r1), "=r"(r2), "=r"(r3) : "r"(addr));
}
__device__ __forceinline__ void mma_f16(float* c, uint32_t a0, uint32_t a1, uint32_t a2, uint32_t a3,
                                        uint32_t b0, uint32_t b1) {
    asm volatile(
        "mma.sync.aligned.m16n8k16.row.col.f32.f16.f16.f32 "
        "{%0,%1,%2,%3}, {%4,%5,%6,%7}, {%8,%9}, {%0,%1,%2,%3};"
        : "+f"(c[0]), "+f"(c[1]), "+f"(c[2]), "+f"(c[3])
        : "r"(a0), "r"(a1), "r"(a2), "r"(a3), "r"(b0), "r"(b1));
}
__device__ __forceinline__ void cp16(uint32_t saddr, const void* gptr) {
    asm volatile("cp.async.cg.shared.global [%0], [%1], 16;" :: "r"(saddr), "l"(gptr));
}
#define CP_COMMIT() asm volatile("cp.async.commit_group;" ::: "memory")
#define CP_WAIT(n)  asm volatile("cp.async.wait_group %0;" :: "n"(n) : "memory")
__device__ __forceinline__ float ex2f(float x) { float y; asm("ex2.approx.f32 %0, %1;" : "=f"(y) : "f"(x)); return y; }
__device__ __forceinline__ uint32_t h2ex2(uint32_t x) {
    uint32_t y; asm("ex2.approx.f16x2 %0, %1;" : "=r"(y) : "r"(x)); return y;
}
__device__ __forceinline__ uint32_t pack_h2(float a, float b) {
    __half2 h = __floats2half2_rn(a, b);
    return *(uint32_t*)&h;
}

// ================= scratch =================
__device__ float g_t1[(size_t)NROWS*D_MODEL];
__device__ float g_h [(size_t)NROWS*D_MODEL];

__device__ __half g_x16 [(size_t)NROWS*D_MODEL];
__device__ __half g_q16 [(size_t)NROWS*D_MODEL];
__device__ __half g_k16 [(size_t)NROWS*D_MODEL];
__device__ __half g_v16 [(size_t)NROWS*D_MODEL];
__device__ __half g_c16 [(size_t)NROWS*D_MODEL];
__device__ __half g_h16 [(size_t)NROWS*D_MODEL];
__device__ __half g_f116[(size_t)NROWS*D_FF];
__device__ __half g_wqkv16[(size_t)3*D_MODEL*D_MODEL];
__device__ __half g_wo16 [(size_t)D_MODEL*D_MODEL];
__device__ __half g_w116 [(size_t)D_FF*D_MODEL];
__device__ __half g_w216 [(size_t)D_MODEL*D_FF];

// ================= conversion kernels =================
__global__ __launch_bounds__(256)
void cvt_f16_kernel(const float* __restrict__ in, __half* __restrict__ out, int n)
{
    int i = (blockIdx.x * 256 + threadIdx.x) * 8;
    if (i >= n) return;
    float4 v0 = *(const float4*)(in + i);
    float4 v1 = *(const float4*)(in + i + 4);
    uint4 o;
    o.x = pack_h2(v0.x, v0.y);
    o.y = pack_h2(v0.z, v0.w);
    o.z = pack_h2(v1.x, v1.y);
    o.w = pack_h2(v1.z, v1.w);
    *(uint4*)(out + i) = o;
}

// ALL weight transposes in one launch (12288 blocks; see R9).
__global__ __launch_bounds__(256)
void transpose_all_kernel(const float* __restrict__ Wq, const float* __restrict__ Wk,
                          const float* __restrict__ Wv, const float* __restrict__ Wo,
                          const float* __restrict__ W1, const float* __restrict__ W2,
                          __half* __restrict__ wqkv, __half* __restrict__ wo,
                          __half* __restrict__ w1,   __half* __restrict__ w2)
{
    __shared__ float ts[32][33];
    const int id = blockIdx.x;
    const float* W; __half* T;
    int K, M, rowoff, bx, by;
    if (id < 4096) {
        int mat = id >> 10, r = id & 1023;
        bx = r & 31; by = r >> 5;
        K = 1024; M = 1024;
        if      (mat == 0) { W = Wq; T = wqkv; rowoff = 0;    }
        else if (mat == 1) { W = Wk; T = wqkv; rowoff = 1024; }
        else if (mat == 2) { W = Wv; T = wqkv; rowoff = 2048; }
        else               { W = Wo; T = wo;   rowoff = 0;    }
    } else if (id < 8192) {
        int r = id - 4096;
        bx = r & 127; by = r >> 7;
        K = 1024; M = 4096; W = W1; T = w1; rowoff = 0;
    } else {
        int r = id - 8192;
        bx = r & 31; by = r >> 5;
        K = 4096; M = 1024; W = W2; T = w2; rowoff = 0;
    }
    const int m0 = bx * 32, k0 = by * 32;
    const int tx = threadIdx.x, ty = threadIdx.y;
    #pragma unroll
    for (int i = 0; i < 4; i++) {
        int k = ty + i*8;
        ts[k][tx] = W[(size_t)(k0+k)*M + m0 + tx];
    }
    __syncthreads();
    #pragma unroll
    for (int i = 0; i < 4; i++) {
        int m = ty + i*8;
        T[(size_t)(rowoff + m0 + m)*K + k0 + tx] = __float2half_rn(ts[tx][m]);
    }
}

// ================= mma.sync fp16 GEMM (3-stage pipeline) ===================
// MODE 0: f32 -> Cf.  MODE 1: relu -> fp16 C0.
// MODE 3: fused QKV: sec0 -> C0 (scaled), sec1 -> C1, sec2 -> C2.
// Smem: 3 stages x (A 16KB | B 16KB) = 96KB. One __syncthreads per chunk.
#define GEMM_SMEM (3*32768)

template<int MODE>
__global__ __launch_bounds__(256, 2)
void gemm_mma(const __half* __restrict__ A16, const __half* __restrict__ B16,
              const float* __restrict__ bias, const float* __restrict__ bias2,
              const float* __restrict__ bias3,
              float* __restrict__ Cf,
              __half* __restrict__ C0, __half* __restrict__ C1, __half* __restrict__ C2,
              int K, int M)
{
    extern __shared__ char sb[];
    const int tid  = threadIdx.x;
    const int wid  = tid >> 5;
    const int lane = tid & 31;
    const int wm   = wid >> 2;
    const int wn   = wid & 3;
    const int brow = blockIdx.y * 128;
    const int bcol = blockIdx.x * 128;
    const uint32_t sbu = smem_u32(sb);

    float acc[4][4][4];
    #pragma unroll
    for (int mf = 0; mf < 4; mf++)
      #pragma unroll
      for (int nf = 0; nf < 4; nf++)
        #pragma unroll
        for (int q = 0; q < 4; q++) acc[mf][nf][q] = 0.f;

    const int NC = K >> 6;
    const __half* srcs[2] = {A16, B16};
    const int bases[2] = {brow, bcol};

    auto prefetch = [&](int c) {
        const int kc = c << 6;
        const uint32_t boff = (uint32_t)(c % 3) * 32768u;
        #pragma unroll
        for (int it = 0; it < 8; it++) {
            int idx  = tid + it*256;
            int tile = idx >> 10;
            int rem  = idx & 1023;
            int r    = rem >> 3;
            int chn  = rem & 7;
            const __half* g = srcs[tile] + (size_t)(bases[tile] + r)*K + kc + chn*8;
            cp16(sbu + boff + (uint32_t)tile*16384u + SWZ128((uint32_t)((r << 7) + (chn << 4))), g);
        }
        CP_COMMIT();
    };

    prefetch(0);
    prefetch(1);

    const int rloc   = (lane & 7) + ((lane >> 3) & 1) * 8;
    const int kpiece = (lane >> 4) << 4;

    for (int c = 0; c < NC; c++) {
        if (c + 1 < NC) CP_WAIT(1); else CP_WAIT(0);
        __syncthreads();
        if (c + 2 < NC) prefetch(c + 2);

        const uint32_t buf = sbu + (uint32_t)(c % 3) * 32768u;
        const uint32_t aB  = buf;
        const uint32_t bB  = buf + 16384u;

        #pragma unroll
        for (int ks = 0; ks < 4; ks++) {
            const uint32_t wb = (uint32_t)(ks*32 + kpiece);
            uint32_t af[4][4];
            #pragma unroll
            for (int mf = 0; mf < 4; mf++) {
                uint32_t off = SWZ128((uint32_t)(((wm*64 + mf*16 + rloc) << 7)) + wb);
                ldsm_x4(af[mf][0], af[mf][1], af[mf][2], af[mf][3], aB + off);
            }
            uint32_t bf[2][4];
            #pragma unroll
            for (int g = 0; g < 2; g++) {
                uint32_t off = SWZ128((uint32_t)(((wn*32 + g*16 + rloc) << 7)) + wb);
                ldsm_x4(bf[g][0], bf[g][1], bf[g][2], bf[g][3], bB + off);
            }
            #pragma unroll
            for (int mf = 0; mf < 4; mf++) {
                #pragma unroll
                for (int g = 0; g < 2; g++) {
                    mma_f16(acc[mf][g*2],   af[mf][0], af[mf][1], af[mf][2], af[mf][3], bf[g][0], bf[g][2]);
                    mma_f16(acc[mf][g*2+1], af[mf][0], af[mf][1], af[mf][2], af[mf][3], bf[g][1], bf[g][3]);
                }
            }
        }
    }

    const int qr = lane >> 2;
    const int qc = (lane & 3) * 2;

    int sec = 0;
    const float* bi = bias;
    __half* Dh = C0;
    int ostride = M;
    float oscale = 1.f;
    if (MODE == 3) {
        sec = bcol >> 10;
        bi  = (sec == 0) ? bias : (sec == 1 ? bias2 : bias3);
        Dh  = (sec == 0) ? C0 : (sec == 1 ? C1 : C2);
        ostride = D_MODEL;
        if (sec == 0) oscale = 0.125f * 1.44269504f;
    }

    #pragma unroll
    for (int mf = 0; mf < 4; mf++) {
        #pragma unroll
        for (int nf = 0; nf < 4; nf++) {
            const int row  = brow + wm*64 + mf*16 + qr;
            const int col  = bcol + wn*32 + nf*8 + qc;
            const int colS = (MODE == 3) ? (col & 1023) : col;
            const float b0 = __ldg(bi + colS), b1 = __ldg(bi + colS + 1);
            float v00 = acc[mf][nf][0] + b0, v01 = acc[mf][nf][1] + b1;
            float v10 = acc[mf][nf][2] + b0, v11 = acc[mf][nf][3] + b1;
            if (MODE == 0) {
                *(float2*)(Cf + (size_t)row*M + colS)     = make_float2(v00, v01);
                *(float2*)(Cf + (size_t)(row+8)*M + colS) = make_float2(v10, v11);
            } else {
                if (MODE == 1) {
                    v00 = fmaxf(v00, 0.f); v01 = fmaxf(v01, 0.f);
                    v10 = fmaxf(v10, 0.f); v11 = fmaxf(v11, 0.f);
                }
                if (MODE == 3) {
                    v00 *= oscale; v01 *= oscale; v10 *= oscale; v11 *= oscale;
                }
                *(uint32_t*)(Dh + (size_t)row*ostride + colS)     = pack_h2(v00, v01);
                *(uint32_t*)(Dh + (size_t)(row+8)*ostride + colS) = pack_h2(v10, v11);
            }
        }
    }
}

// ================= mma.sync fp16 flash attention (3-stage KV) ==============
// BQ=128, BK=64, dk=64. Smem: Q 16KB + 3 x (K 8KB | V 8KB) = 64KB.
// One __syncthreads per key tile.
#define ATT_SMEM (16384 + 3*16384)
#define ONES_H2 0x3C003C00u

__global__ __launch_bounds__(256, 2)
void attention_mma(const __half* __restrict__ Q16,
                   const __half* __restrict__ K16, const __half* __restrict__ V16,
                   __half* __restrict__ ctx16)
{
    extern __shared__ char sb[];
    const uint32_t sbu = smem_u32(sb);
    const int tid  = threadIdx.x;
    const int wid  = tid >> 5;
    const int lane = tid & 31;
    const int bh   = blockIdx.y;
    const int b    = bh >> 4;
    const int hh   = bh & 15;
    const int q0   = blockIdx.x * 128;
    const size_t rbase = (size_t)b*SEQ*D_MODEL + (size_t)hh*DKH;

    const __half* kvsrc[2] = {K16, V16};
    const int NT = SEQ / 64;

    auto prefetch_kv = [&](int t) {
        const int s0 = t * 64;
        const uint32_t boff = 16384u + (uint32_t)(t % 3) * 16384u;
        #pragma unroll
        for (int it = 0; it < 4; it++) {
            int idx  = tid + it*256;
            int tile = idx >> 9;
            int rem  = idx & 511;
            int r    = rem >> 3;
            int chn  = rem & 7;
            const __half* g = kvsrc[tile] + rbase + (size_t)(s0+r)*D_MODEL + chn*8;
            cp16(sbu + boff + (uint32_t)tile*8192u + SWZ128((uint32_t)((r << 7) + (chn << 4))), g);
        }
        CP_COMMIT();
    };

    // Q group first, then KV tiles 0 and 1
    {
        #pragma unroll
        for (int it = 0; it < 4; it++) {
            int idx = tid + it*256;
            int r   = idx >> 3;
            int chn = idx & 7;
            const __half* g = Q16 + rbase + (size_t)(q0 + r)*D_MODEL + chn*8;
            cp16(sbu + SWZ128((uint32_t)((r << 7) + (chn << 4))), g);
        }
        CP_COMMIT();
    }
    prefetch_kv(0);
    prefetch_kv(1);

    const int rloc   = (lane & 7) + ((lane >> 3) & 1) * 8;
    const int kpiece = (lane >> 4) << 4;

    // Q fragments: wait for Q group (allow KV tiles 0,1 pending)
    CP_WAIT(2);
    __syncthreads();
    uint32_t qf[4][4];
    #pragma unroll
    for (int ks = 0; ks < 4; ks++) {
        uint32_t off = SWZ128((uint32_t)(((wid*16 + rloc) << 7) + ks*32 + kpiece));
        ldsm_x4(qf[ks][0], qf[ks][1], qf[ks][2], qf[ks][3], sbu + off);
    }

    float O[8][4];
    #pragma unroll
    for (int nt = 0; nt < 8; nt++)
      #pragma unroll
      for (int q = 0; q < 4; q++) O[nt][q] = 0.f;
    float m0 = -1e30f, m1 = -1e30f, l0 = 0.f, l1 = 0.f;

    for (int t = 0; t < NT; t++) {
        if (t + 1 < NT) CP_WAIT(1); else CP_WAIT(0);
        __syncthreads();
        if (t + 2 < NT) prefetch_kv(t + 2);

        const uint32_t kb = sbu + 16384u + (uint32_t)(t % 3) * 16384u;
        const uint32_t vb = kb + 8192u;

        // ---- S = Q K^T (log2-domain, Q prescaled) ----
        float sc[8][4];
        #pragma unroll
        for (int nt = 0; nt < 8; nt++)
          #pragma unroll
          for (int q = 0; q < 4; q++) sc[nt][q] = 0.f;

        #pragma unroll
        for (int ks = 0; ks < 4; ks++) {
            #pragma unroll
            for (int g = 0; g < 4; g++) {
                uint32_t kf[4];
                uint32_t off = SWZ128((uint32_t)(((g*16 + rloc) << 7) + ks*32 + kpiece));
                ldsm_x4(kf[0], kf[1], kf[2], kf[3], kb + off);
                mma_f16(sc[g*2],   qf[ks][0], qf[ks][1], qf[ks][2], qf[ks][3], kf[0], kf[2]);
                mma_f16(sc[g*2+1], qf[ks][0], qf[ks][1], qf[ks][2], qf[ks][3], kf[1], kf[3]);
            }
        }

        // ---- online softmax: max in f32, exp in f16x2 ----
        float mx0 = -1e30f, mx1 = -1e30f;
        #pragma unroll
        for (int nt = 0; nt < 8; nt++) {
            mx0 = fmaxf(mx0, fmaxf(sc[nt][0], sc[nt][1]));
            mx1 = fmaxf(mx1, fmaxf(sc[nt][2], sc[nt][3]));
        }
        mx0 = fmaxf(mx0, __shfl_xor_sync(0xffffffffu, mx0, 1));
        mx0 = fmaxf(mx0, __shfl_xor_sync(0xffffffffu, mx0, 2));
        mx1 = fmaxf(mx1, __shfl_xor_sync(0xffffffffu, mx1, 1));
        mx1 = fmaxf(mx1, __shfl_xor_sync(0xffffffffu, mx1, 2));
        const float mn0 = fmaxf(m0, mx0), mn1 = fmaxf(m1, mx1);
        const float a0 = ex2f(m0 - mn0), a1 = ex2f(m1 - mn1);

        uint32_t pl[8], ph[8];
        #pragma unroll
        for (int nt = 0; nt < 8; nt++) {
            pl[nt] = h2ex2(pack_h2(sc[nt][0] - mn0, sc[nt][1] - mn0));
            ph[nt] = h2ex2(pack_h2(sc[nt][2] - mn1, sc[nt][3] - mn1));
        }

        // row sums of quantized P via tensor core (B = ones)
        float sacc[4] = {0.f, 0.f, 0.f, 0.f};
        #pragma unroll
        for (int ks = 0; ks < 4; ks++)
            mma_f16(sacc, pl[2*ks], ph[2*ks], pl[2*ks+1], ph[2*ks+1], ONES_H2, ONES_H2);

        l0 = l0*a0 + sacc[0];
        l1 = l1*a1 + sacc[2];
        m0 = mn0; m1 = mn1;
        #pragma unroll
        for (int nt = 0; nt < 8; nt++) {
            O[nt][0] *= a0; O[nt][1] *= a0;
            O[nt][2] *= a1; O[nt][3] *= a1;
        }

        // ---- O += P V ----
        #pragma unroll
        for (int ks = 0; ks < 4; ks++) {
            const int e = 2*ks, o = 2*ks + 1;
            #pragma unroll
            for (int dg = 0; dg < 4; dg++) {
                uint32_t vf[4];
                uint32_t off = SWZ128((uint32_t)(((ks*16 + rloc) << 7) + dg*32 + kpiece));
                ldsm_x4_t(vf[0], vf[1], vf[2], vf[3], vb + off);
                mma_f16(O[dg*2],   pl[e], ph[e], pl[o], ph[o], vf[0], vf[1]);
                mma_f16(O[dg*2+1], pl[e], ph[e], pl[o], ph[o], vf[2], vf[3]);
            }
        }
    }

    // ---- epilogue ----
    const float i0 = 1.f / l0, i1 = 1.f / l1;
    const int qr = lane >> 2;
    const int qc = (lane & 3) * 2;
    const int rowA = q0 + wid*16 + qr;
    #pragma unroll
    for (int nt = 0; nt < 8; nt++) {
        float v0 = O[nt][0]*i0, v1 = O[nt][1]*i0;
        float v2 = O[nt][2]*i1, v3 = O[nt][3]*i1;
        size_t oA = rbase + (size_t)rowA*D_MODEL + nt*8 + qc;
        size_t oB = oA + 8*D_MODEL;
        *(uint32_t*)(ctx16 + oA) = pack_h2(v0, v1);
        *(uint32_t*)(ctx16 + oB) = pack_h2(v2, v3);
    }
}

// ================= residual add + LayerNorm ================================
template<bool EMIT16>
__global__ __launch_bounds__(256)
void add_ln_kernel(const float* __restrict__ A, const float* __restrict__ Bm,
                   const float* __restrict__ gamma, const float* __restrict__ beta,
                   float* __restrict__ out, __half* __restrict__ o16)
{
    __shared__ float sh[8];
    const int row = blockIdx.x;
    const int tid = threadIdx.x;
    const float* a  = A  + (size_t)row*D_MODEL;
    const float* bb = Bm + (size_t)row*D_MODEL;
    float v[4];
    float s = 0.f;
    #pragma unroll
    for (int i = 0; i < 4; i++) { int c = tid + i*256; v[i] = a[c] + bb[c]; s += v[i]; }
    #pragma unroll
    for (int o = 16; o; o >>= 1) s += __shfl_xor_sync(0xffffffffu, s, o);
    if ((tid & 31) == 0) sh[tid >> 5] = s;
    __syncthreads();
    float tot = 0.f;
    #pragma unroll
    for (int i = 0; i < 8; i++) tot += sh[i];
    const float mean = tot * (1.f/(float)D_MODEL);
    float s2 = 0.f;
    #pragma unroll
    for (int i = 0; i < 4; i++) { float d = v[i]-mean; s2 += d*d; }
    #pragma unroll
    for (int o = 16; o; o >>= 1) s2 += __shfl_xor_sync(0xffffffffu, s2, o);
    __syncthreads();
    if ((tid & 31) == 0) sh[tid >> 5] = s2;
    __syncthreads();
    float tot2 = 0.f;
    #pragma unroll
    for (int i = 0; i < 8; i++) tot2 += sh[i];
    const float inv = 1.f / (sqrtf(tot2 * (1.f/(float)D_MODEL)) + LN_EPS);
    #pragma unroll
    for (int i = 0; i < 4; i++) {
        int c = tid + i*256;
        float r = gamma[c]*(v[i]-mean)*inv + beta[c];
        out[(size_t)row*D_MODEL + c] = r;
        if (EMIT16) o16[(size_t)row*D_MODEL + c] = __float2half_rn(r);
    }
}

// ================= launcher =================
extern "C" void kernel_launch(void* const* d_in, const int* in_sizes, int n_in,
                              void* d_out, int out_size)
{
    const float* x   = (const float*)d_in[0];
    const float* Wq  = (const float*)d_in[1];
    const float* bq  = (const float*)d_in[2];
    const float* Wk  = (const float*)d_in[3];
    const float* bk  = (const float*)d_in[4];
    const float* Wv  = (const float*)d_in[5];
    const float* bv  = (const float*)d_in[6];
    const float* Wo  = (const float*)d_in[7];
    const float* bo  = (const float*)d_in[8];
    const float* W1  = (const float*)d_in[9];
    const float* b1  = (const float*)d_in[10];
    const float* W2  = (const float*)d_in[11];
    const float* b2  = (const float*)d_in[12];
    const float* g1  = (const float*)d_in[13];
    const float* be1 = (const float*)d_in[14];
    const float* g2  = (const float*)d_in[15];
    const float* be2 = (const float*)d_in[16];
    float* out = (float*)d_out;

    float *t1,*h;
    __half *x16,*q16,*k16,*v16,*c16,*h16,*f116,*wqkv16,*wo16,*w116,*w216;
    cudaGetSymbolAddress((void**)&t1,     g_t1);
    cudaGetSymbolAddress((void**)&h,      g_h);
    cudaGetSymbolAddress((void**)&x16,    g_x16);
    cudaGetSymbolAddress((void**)&q16,    g_q16);
    cudaGetSymbolAddress((void**)&k16,    g_k16);
    cudaGetSymbolAddress((void**)&v16,    g_v16);
    cudaGetSymbolAddress((void**)&c16,    g_c16);
    cudaGetSymbolAddress((void**)&h16,    g_h16);
    cudaGetSymbolAddress((void**)&f116,   g_f116);
    cudaGetSymbolAddress((void**)&wqkv16, g_wqkv16);
    cudaGetSymbolAddress((void**)&wo16,   g_wo16);
    cudaGetSymbolAddress((void**)&w116,   g_w116);
    cudaGetSymbolAddress((void**)&w216,   g_w216);

    cudaFuncSetAttribute(gemm_mma<0>, cudaFuncAttributeMaxDynamicSharedMemorySize, GEMM_SMEM);
    cudaFuncSetAttribute(gemm_mma<1>, cudaFuncAttributeMaxDynamicSharedMemorySize, GEMM_SMEM);
    cudaFuncSetAttribute(gemm_mma<3>, cudaFuncAttributeMaxDynamicSharedMemorySize, GEMM_SMEM);
    cudaFuncSetAttribute(attention_mma, cudaFuncAttributeMaxDynamicSharedMemorySize, ATT_SMEM);

    const int nX = NROWS*D_MODEL;
    dim3 tt(32, 8);
    dim3 thr(256);

    cvt_f16_kernel<<<nX/2048, 256>>>(x, x16, nX);
    transpose_all_kernel<<<12288, tt>>>(Wq, Wk, Wv, Wo, W1, W2,
                                        wqkv16, wo16, w116, w216);
    // fused QKV (Q prescaled fp16, K/V fp16)
    gemm_mma<3><<<dim3(24, 32), thr, GEMM_SMEM>>>(x16, wqkv16, bq, bk, bv,
                                                  nullptr, q16, k16, v16, D_MODEL, D_MODEL);
    // attention
    attention_mma<<<dim3(SEQ/128, BATCH*NHEADS), thr, ATT_SMEM>>>(q16, k16, v16, c16);
    // Wo -> t1 (f32)
    gemm_mma<0><<<dim3(8, 32), thr, GEMM_SMEM>>>(c16, wo16, bo, nullptr, nullptr,
                                                 t1, nullptr, nullptr, nullptr, D_MODEL, D_MODEL);
    // LN1 -> h (f32) + h16
    add_ln_kernel<true><<<NROWS, thr>>>(x, t1, g1, be1, h, h16);
    // FF1 (relu -> fp16)
    gemm_mma<1><<<dim3(32, 32), thr, GEMM_SMEM>>>(h16, w116, b1, nullptr, nullptr,
                                                  nullptr, f116, nullptr, nullptr, D_MODEL, D_FF);
    // FF2 -> t1 (f32)
    gemm_mma<0><<<dim3(8, 32), thr, GEMM_SMEM>>>(f116, w216, b2, nullptr, nullptr,
                                                 t1, nullptr, nullptr, nullptr, D_FF, D_MODEL);
    // LN2 -> out
    add_ln_kernel<false><<<NROWS, thr>>>(h, t1, g2, be2, out, nullptr);
}

// round 13
// speedup vs baseline: 1.0111x; 1.0111x over previous
#include <cuda_runtime.h>
#include <cuda_fp16.h>
#include <math.h>
#include <stdint.h>

#define D_MODEL 1024
#define NHEADS  16
#define DKH     64
#define D_FF    4096
#define BATCH   2
#define SEQ     2048
#define NROWS   (BATCH*SEQ)
#define LN_EPS  1e-6f

#define SWZ128(x) ((x) ^ (((x) >> 3) & 0x70))

// ================= PTX helpers ============================================
__device__ __forceinline__ uint32_t smem_u32(const void* p) {
    uint32_t a;
    asm("{ .reg .u64 t; cvta.to.shared.u64 t, %1; cvt.u32.u64 %0, t; }" : "=r"(a) : "l"(p));
    return a;
}
__device__ __forceinline__ void ldsm_x4(uint32_t& r0, uint32_t& r1, uint32_t& r2, uint32_t& r3, uint32_t addr) {
    asm volatile("ldmatrix.sync.aligned.m8n8.x4.shared.b16 {%0,%1,%2,%3}, [%4];"
                 : "=r"(r0), "=r"(r1), "=r"(r2), "=r"(r3) : "r"(addr));
}
__device__ __forceinline__ void ldsm_x4_t(uint32_t& r0, uint32_t& r1, uint32_t& r2, uint32_t& r3, uint32_t addr) {
    asm volatile("ldmatrix.sync.aligned.m8n8.x4.trans.shared.b16 {%0,%1,%2,%3}, [%4];"
                 : "=r"(r0), "=r"(r1), "=r"(r2), "=r"(r3) : "r"(addr));
}
__device__ __forceinline__ void mma_f16(float* c, uint32_t a0, uint32_t a1, uint32_t a2, uint32_t a3,
                                        uint32_t b0, uint32_t b1) {
    asm volatile(
        "mma.sync.aligned.m16n8k16.row.col.f32.f16.f16.f32 "
        "{%0,%1,%2,%3}, {%4,%5,%6,%7}, {%8,%9}, {%0,%1,%2,%3};"
        : "+f"(c[0]), "+f"(c[1]), "+f"(c[2]), "+f"(c[3])
        : "r"(a0), "r"(a1), "r"(a2), "r"(a3), "r"(b0), "r"(b1));
}
__device__ __forceinline__ void cp16(uint32_t saddr, const void* gptr) {
    asm volatile("cp.async.cg.shared.global [%0], [%1], 16;" :: "r"(saddr), "l"(gptr));
}
#define CP_COMMIT() asm volatile("cp.async.commit_group;" ::: "memory")
#define CP_WAIT(n)  asm volatile("cp.async.wait_group %0;" :: "n"(n) : "memory")
__device__ __forceinline__ float ex2f(float x) { float y; asm("ex2.approx.f32 %0, %1;" : "=f"(y) : "f"(x)); return y; }
__device__ __forceinline__ uint32_t h2ex2(uint32_t x) {
    uint32_t y; asm("ex2.approx.f16x2 %0, %1;" : "=r"(y) : "r"(x)); return y;
}
__device__ __forceinline__ uint32_t pack_h2(float a, float b) {
    __half2 h = __floats2half2_rn(a, b);
    return *(uint32_t*)&h;
}

// ================= scratch =================
__device__ float g_t1[(size_t)NROWS*D_MODEL];
__device__ float g_h [(size_t)NROWS*D_MODEL];

__device__ __half g_x16 [(size_t)NROWS*D_MODEL];
__device__ __half g_q16 [(size_t)NROWS*D_MODEL];
__device__ __half g_k16 [(size_t)NROWS*D_MODEL];
__device__ __half g_v16 [(size_t)NROWS*D_MODEL];
__device__ __half g_c16 [(size_t)NROWS*D_MODEL];
__device__ __half g_h16 [(size_t)NROWS*D_MODEL];
__device__ __half g_f116[(size_t)NROWS*D_FF];
__device__ __half g_wqkv16[(size_t)3*D_MODEL*D_MODEL];
__device__ __half g_wo16 [(size_t)D_MODEL*D_MODEL];
__device__ __half g_w116 [(size_t)D_FF*D_MODEL];
__device__ __half g_w216 [(size_t)D_MODEL*D_FF];

// ================= conversion kernels =================
__global__ __launch_bounds__(256)
void cvt_f16_kernel(const float* __restrict__ in, __half* __restrict__ out, int n)
{
    int i = (blockIdx.x * 256 + threadIdx.x) * 8;
    if (i >= n) return;
    float4 v0 = *(const float4*)(in + i);
    float4 v1 = *(const float4*)(in + i + 4);
    uint4 o;
    o.x = pack_h2(v0.x, v0.y);
    o.y = pack_h2(v0.z, v0.w);
    o.z = pack_h2(v1.x, v1.y);
    o.w = pack_h2(v1.z, v1.w);
    *(uint4*)(out + i) = o;
}

// ALL weight transposes in one launch (12288 blocks).
__global__ __launch_bounds__(256)
void transpose_all_kernel(const float* __restrict__ Wq, const float* __restrict__ Wk,
                          const float* __restrict__ Wv, const float* __restrict__ Wo,
                          const float* __restrict__ W1, const float* __restrict__ W2,
                          __half* __restrict__ wqkv, __half* __restrict__ wo,
                          __half* __restrict__ w1,   __half* __restrict__ w2)
{
    __shared__ float ts[32][33];
    const int id = blockIdx.x;
    const float* W; __half* T;
    int K, M, rowoff, bx, by;
    if (id < 4096) {
        int mat = id >> 10, r = id & 1023;
        bx = r & 31; by = r >> 5;
        K = 1024; M = 1024;
        if      (mat == 0) { W = Wq; T = wqkv; rowoff = 0;    }
        else if (mat == 1) { W = Wk; T = wqkv; rowoff = 1024; }
        else if (mat == 2) { W = Wv; T = wqkv; rowoff = 2048; }
        else               { W = Wo; T = wo;   rowoff = 0;    }
    } else if (id < 8192) {
        int r = id - 4096;
        bx = r & 127; by = r >> 7;
        K = 1024; M = 4096; W = W1; T = w1; rowoff = 0;
    } else {
        int r = id - 8192;
        bx = r & 31; by = r >> 5;
        K = 4096; M = 1024; W = W2; T = w2; rowoff = 0;
    }
    const int m0 = bx * 32, k0 = by * 32;
    const int tx = threadIdx.x, ty = threadIdx.y;
    #pragma unroll
    for (int i = 0; i < 4; i++) {
        int k = ty + i*8;
        ts[k][tx] = W[(size_t)(k0+k)*M + m0 + tx];
    }
    __syncthreads();
    #pragma unroll
    for (int i = 0; i < 4; i++) {
        int m = ty + i*8;
        T[(size_t)(rowoff + m0 + m)*K + k0 + tx] = __float2half_rn(ts[tx][m]);
    }
}

// ================= mma.sync fp16 GEMM (3-stage pipeline) ===================
#define GEMM_SMEM (3*32768)

template<int MODE>
__global__ __launch_bounds__(256, 2)
void gemm_mma(const __half* __restrict__ A16, const __half* __restrict__ B16,
              const float* __restrict__ bias, const float* __restrict__ bias2,
              const float* __restrict__ bias3,
              float* __restrict__ Cf,
              __half* __restrict__ C0, __half* __restrict__ C1, __half* __restrict__ C2,
              int K, int M)
{
    extern __shared__ char sb[];
    const int tid  = threadIdx.x;
    const int wid  = tid >> 5;
    const int lane = tid & 31;
    const int wm   = wid >> 2;
    const int wn   = wid & 3;
    const int brow = blockIdx.y * 128;
    const int bcol = blockIdx.x * 128;
    const uint32_t sbu = smem_u32(sb);

    float acc[4][4][4];
    #pragma unroll
    for (int mf = 0; mf < 4; mf++)
      #pragma unroll
      for (int nf = 0; nf < 4; nf++)
        #pragma unroll
        for (int q = 0; q < 4; q++) acc[mf][nf][q] = 0.f;

    const int NC = K >> 6;
    const __half* srcs[2] = {A16, B16};
    const int bases[2] = {brow, bcol};

    auto prefetch = [&](int c) {
        const int kc = c << 6;
        const uint32_t boff = (uint32_t)(c % 3) * 32768u;
        #pragma unroll
        for (int it = 0; it < 8; it++) {
            int idx  = tid + it*256;
            int tile = idx >> 10;
            int rem  = idx & 1023;
            int r    = rem >> 3;
            int chn  = rem & 7;
            const __half* g = srcs[tile] + (size_t)(bases[tile] + r)*K + kc + chn*8;
            cp16(sbu + boff + (uint32_t)tile*16384u + SWZ128((uint32_t)((r << 7) + (chn << 4))), g);
        }
        CP_COMMIT();
    };

    prefetch(0);
    prefetch(1);

    const int rloc   = (lane & 7) + ((lane >> 3) & 1) * 8;
    const int kpiece = (lane >> 4) << 4;

    for (int c = 0; c < NC; c++) {
        if (c + 1 < NC) CP_WAIT(1); else CP_WAIT(0);
        __syncthreads();
        if (c + 2 < NC) prefetch(c + 2);

        const uint32_t buf = sbu + (uint32_t)(c % 3) * 32768u;
        const uint32_t aB  = buf;
        const uint32_t bB  = buf + 16384u;

        #pragma unroll
        for (int ks = 0; ks < 4; ks++) {
            const uint32_t wb = (uint32_t)(ks*32 + kpiece);
            uint32_t af[4][4];
            #pragma unroll
            for (int mf = 0; mf < 4; mf++) {
                uint32_t off = SWZ128((uint32_t)(((wm*64 + mf*16 + rloc) << 7)) + wb);
                ldsm_x4(af[mf][0], af[mf][1], af[mf][2], af[mf][3], aB + off);
            }
            uint32_t bf[2][4];
            #pragma unroll
            for (int g = 0; g < 2; g++) {
                uint32_t off = SWZ128((uint32_t)(((wn*32 + g*16 + rloc) << 7)) + wb);
                ldsm_x4(bf[g][0], bf[g][1], bf[g][2], bf[g][3], bB + off);
            }
            #pragma unroll
            for (int mf = 0; mf < 4; mf++) {
                #pragma unroll
                for (int g = 0; g < 2; g++) {
                    mma_f16(acc[mf][g*2],   af[mf][0], af[mf][1], af[mf][2], af[mf][3], bf[g][0], bf[g][2]);
                    mma_f16(acc[mf][g*2+1], af[mf][0], af[mf][1], af[mf][2], af[mf][3], bf[g][1], bf[g][3]);
                }
            }
        }
    }

    const int qr = lane >> 2;
    const int qc = (lane & 3) * 2;

    int sec = 0;
    const float* bi = bias;
    __half* Dh = C0;
    int ostride = M;
    float oscale = 1.f;
    if (MODE == 3) {
        sec = bcol >> 10;
        bi  = (sec == 0) ? bias : (sec == 1 ? bias2 : bias3);
        Dh  = (sec == 0) ? C0 : (sec == 1 ? C1 : C2);
        ostride = D_MODEL;
        if (sec == 0) oscale = 0.125f * 1.44269504f;
    }

    #pragma unroll
    for (int mf = 0; mf < 4; mf++) {
        #pragma unroll
        for (int nf = 0; nf < 4; nf++) {
            const int row  = brow + wm*64 + mf*16 + qr;
            const int col  = bcol + wn*32 + nf*8 + qc;
            const int colS = (MODE == 3) ? (col & 1023) : col;
            const float b0 = __ldg(bi + colS), b1 = __ldg(bi + colS + 1);
            float v00 = acc[mf][nf][0] + b0, v01 = acc[mf][nf][1] + b1;
            float v10 = acc[mf][nf][2] + b0, v11 = acc[mf][nf][3] + b1;
            if (MODE == 0) {
                *(float2*)(Cf + (size_t)row*M + colS)     = make_float2(v00, v01);
                *(float2*)(Cf + (size_t)(row+8)*M + colS) = make_float2(v10, v11);
            } else {
                if (MODE == 1) {
                    v00 = fmaxf(v00, 0.f); v01 = fmaxf(v01, 0.f);
                    v10 = fmaxf(v10, 0.f); v11 = fmaxf(v11, 0.f);
                }
                if (MODE == 3) {
                    v00 *= oscale; v01 *= oscale; v10 *= oscale; v11 *= oscale;
                }
                *(uint32_t*)(Dh + (size_t)row*ostride + colS)     = pack_h2(v00, v01);
                *(uint32_t*)(Dh + (size_t)(row+8)*ostride + colS) = pack_h2(v10, v11);
            }
        }
    }
}

// ================= mma.sync fp16 flash attention ===========================
// 128 threads, 4 warps; warp w owns 32 query rows (2 m16 frags).
// K/V fragments loaded ONCE per warp, each feeding 4 MMAs (was 2).
// Smem: Q 16KB + 3 x (K 8KB | V 8KB) = 64KB. 3-stage KV, one sync/tile.
#define ATT_SMEM (16384 + 3*16384)
#define ONES_H2 0x3C003C00u

__global__ __launch_bounds__(128, 2)
void attention_mma(const __half* __restrict__ Q16,
                   const __half* __restrict__ K16, const __half* __restrict__ V16,
                   __half* __restrict__ ctx16)
{
    extern __shared__ char sb[];
    const uint32_t sbu = smem_u32(sb);
    const int tid  = threadIdx.x;
    const int wid  = tid >> 5;          // 0..3
    const int lane = tid & 31;
    const int bh   = blockIdx.y;
    const int b    = bh >> 4;
    const int hh   = bh & 15;
    const int q0   = blockIdx.x * 128;
    const size_t rbase = (size_t)b*SEQ*D_MODEL + (size_t)hh*DKH;

    const __half* kvsrc[2] = {K16, V16};
    const int NT = SEQ / 64;

    auto prefetch_kv = [&](int t) {
        const int s0 = t * 64;
        const uint32_t boff = 16384u + (uint32_t)(t % 3) * 16384u;
        #pragma unroll
        for (int it = 0; it < 8; it++) {
            int idx  = tid + it*128;
            int tile = idx >> 9;
            int rem  = idx & 511;
            int r    = rem >> 3;
            int chn  = rem & 7;
            const __half* g = kvsrc[tile] + rbase + (size_t)(s0+r)*D_MODEL + chn*8;
            cp16(sbu + boff + (uint32_t)tile*8192u + SWZ128((uint32_t)((r << 7) + (chn << 4))), g);
        }
        CP_COMMIT();
    };

    // Q group first, then KV tiles 0 and 1
    {
        #pragma unroll
        for (int it = 0; it < 8; it++) {
            int idx = tid + it*128;
            int r   = idx >> 3;
            int chn = idx & 7;
            const __half* g = Q16 + rbase + (size_t)(q0 + r)*D_MODEL + chn*8;
            cp16(sbu + SWZ128((uint32_t)((r << 7) + (chn << 4))), g);
        }
        CP_COMMIT();
    }
    prefetch_kv(0);
    prefetch_kv(1);

    const int rloc   = (lane & 7) + ((lane >> 3) & 1) * 8;
    const int kpiece = (lane >> 4) << 4;

    // Q fragments: 2 row-frags x 4 k-steps
    CP_WAIT(2);
    __syncthreads();
    uint32_t qf[2][4][4];
    #pragma unroll
    for (int mfr = 0; mfr < 2; mfr++) {
        #pragma unroll
        for (int ks = 0; ks < 4; ks++) {
            uint32_t off = SWZ128((uint32_t)(((wid*32 + mfr*16 + rloc) << 7) + ks*32 + kpiece));
            ldsm_x4(qf[mfr][ks][0], qf[mfr][ks][1], qf[mfr][ks][2], qf[mfr][ks][3], sbu + off);
        }
    }

    float O[2][8][4];
    #pragma unroll
    for (int mfr = 0; mfr < 2; mfr++)
      #pragma unroll
      for (int nt = 0; nt < 8; nt++)
        #pragma unroll
        for (int q = 0; q < 4; q++) O[mfr][nt][q] = 0.f;
    float mr[2][2] = {{-1e30f,-1e30f},{-1e30f,-1e30f}};
    float lr[2][2] = {{0.f,0.f},{0.f,0.f}};

    for (int t = 0; t < NT; t++) {
        if (t + 1 < NT) CP_WAIT(1); else CP_WAIT(0);
        __syncthreads();
        if (t + 2 < NT) prefetch_kv(t + 2);

        const uint32_t kb = sbu + 16384u + (uint32_t)(t % 3) * 16384u;
        const uint32_t vb = kb + 8192u;

        // ---- S = Q K^T (each kf load feeds 4 MMAs) ----
        float sc[2][8][4];
        #pragma unroll
        for (int mfr = 0; mfr < 2; mfr++)
          #pragma unroll
          for (int nt = 0; nt < 8; nt++)
            #pragma unroll
            for (int q = 0; q < 4; q++) sc[mfr][nt][q] = 0.f;

        #pragma unroll
        for (int ks = 0; ks < 4; ks++) {
            #pragma unroll
            for (int g = 0; g < 4; g++) {
                uint32_t kf[4];
                uint32_t off = SWZ128((uint32_t)(((g*16 + rloc) << 7) + ks*32 + kpiece));
                ldsm_x4(kf[0], kf[1], kf[2], kf[3], kb + off);
                #pragma unroll
                for (int mfr = 0; mfr < 2; mfr++) {
                    mma_f16(sc[mfr][g*2],   qf[mfr][ks][0], qf[mfr][ks][1], qf[mfr][ks][2], qf[mfr][ks][3], kf[0], kf[2]);
                    mma_f16(sc[mfr][g*2+1], qf[mfr][ks][0], qf[mfr][ks][1], qf[mfr][ks][2], qf[mfr][ks][3], kf[1], kf[3]);
                }
            }
        }

        // ---- online softmax per row-frag ----
        uint32_t pl[2][8], ph[2][8];
        #pragma unroll
        for (int mfr = 0; mfr < 2; mfr++) {
            float mx0 = -1e30f, mx1 = -1e30f;
            #pragma unroll
            for (int nt = 0; nt < 8; nt++) {
                mx0 = fmaxf(mx0, fmaxf(sc[mfr][nt][0], sc[mfr][nt][1]));
                mx1 = fmaxf(mx1, fmaxf(sc[mfr][nt][2], sc[mfr][nt][3]));
            }
            mx0 = fmaxf(mx0, __shfl_xor_sync(0xffffffffu, mx0, 1));
            mx0 = fmaxf(mx0, __shfl_xor_sync(0xffffffffu, mx0, 2));
            mx1 = fmaxf(mx1, __shfl_xor_sync(0xffffffffu, mx1, 1));
            mx1 = fmaxf(mx1, __shfl_xor_sync(0xffffffffu, mx1, 2));
            const float mn0 = fmaxf(mr[mfr][0], mx0), mn1 = fmaxf(mr[mfr][1], mx1);
            const float a0 = ex2f(mr[mfr][0] - mn0), a1 = ex2f(mr[mfr][1] - mn1);

            #pragma unroll
            for (int nt = 0; nt < 8; nt++) {
                pl[mfr][nt] = h2ex2(pack_h2(sc[mfr][nt][0] - mn0, sc[mfr][nt][1] - mn0));
                ph[mfr][nt] = h2ex2(pack_h2(sc[mfr][nt][2] - mn1, sc[mfr][nt][3] - mn1));
            }

            float sacc[4] = {0.f, 0.f, 0.f, 0.f};
            #pragma unroll
            for (int ks = 0; ks < 4; ks++)
                mma_f16(sacc, pl[mfr][2*ks], ph[mfr][2*ks], pl[mfr][2*ks+1], ph[mfr][2*ks+1], ONES_H2, ONES_H2);

            lr[mfr][0] = lr[mfr][0]*a0 + sacc[0];
            lr[mfr][1] = lr[mfr][1]*a1 + sacc[2];
            mr[mfr][0] = mn0; mr[mfr][1] = mn1;
            #pragma unroll
            for (int nt = 0; nt < 8; nt++) {
                O[mfr][nt][0] *= a0; O[mfr][nt][1] *= a0;
                O[mfr][nt][2] *= a1; O[mfr][nt][3] *= a1;
            }
        }

        // ---- O += P V (each vf load feeds 4 MMAs) ----
        #pragma unroll
        for (int ks = 0; ks < 4; ks++) {
            const int e = 2*ks, o = 2*ks + 1;
            #pragma unroll
            for (int dg = 0; dg < 4; dg++) {
                uint32_t vf[4];
                uint32_t off = SWZ128((uint32_t)(((ks*16 + rloc) << 7) + dg*32 + kpiece));
                ldsm_x4_t(vf[0], vf[1], vf[2], vf[3], vb + off);
                #pragma unroll
                for (int mfr = 0; mfr < 2; mfr++) {
                    mma_f16(O[mfr][dg*2],   pl[mfr][e], ph[mfr][e], pl[mfr][o], ph[mfr][o], vf[0], vf[1]);
                    mma_f16(O[mfr][dg*2+1], pl[mfr][e], ph[mfr][e], pl[mfr][o], ph[mfr][o], vf[2], vf[3]);
                }
            }
        }
    }

    // ---- epilogue ----
    const int qr = lane >> 2;
    const int qc = (lane & 3) * 2;
    #pragma unroll
    for (int mfr = 0; mfr < 2; mfr++) {
        const float i0 = 1.f / lr[mfr][0], i1 = 1.f / lr[mfr][1];
        const int rowA = q0 + wid*32 + mfr*16 + qr;
        #pragma unroll
        for (int nt = 0; nt < 8; nt++) {
            float v0 = O[mfr][nt][0]*i0, v1 = O[mfr][nt][1]*i0;
            float v2 = O[mfr][nt][2]*i1, v3 = O[mfr][nt][3]*i1;
            size_t oA = rbase + (size_t)rowA*D_MODEL + nt*8 + qc;
            size_t oB = oA + 8*D_MODEL;
            *(uint32_t*)(ctx16 + oA) = pack_h2(v0, v1);
            *(uint32_t*)(ctx16 + oB) = pack_h2(v2, v3);
        }
    }
}

// ================= residual add + LayerNorm ================================
template<bool EMIT16>
__global__ __launch_bounds__(256)
void add_ln_kernel(const float* __restrict__ A, const float* __restrict__ Bm,
                   const float* __restrict__ gamma, const float* __restrict__ beta,
                   float* __restrict__ out, __half* __restrict__ o16)
{
    __shared__ float sh[8];
    const int row = blockIdx.x;
    const int tid = threadIdx.x;
    const float* a  = A  + (size_t)row*D_MODEL;
    const float* bb = Bm + (size_t)row*D_MODEL;
    float v[4];
    float s = 0.f;
    #pragma unroll
    for (int i = 0; i < 4; i++) { int c = tid + i*256; v[i] = a[c] + bb[c]; s += v[i]; }
    #pragma unroll
    for (int o = 16; o; o >>= 1) s += __shfl_xor_sync(0xffffffffu, s, o);
    if ((tid & 31) == 0) sh[tid >> 5] = s;
    __syncthreads();
    float tot = 0.f;
    #pragma unroll
    for (int i = 0; i < 8; i++) tot += sh[i];
    const float mean = tot * (1.f/(float)D_MODEL);
    float s2 = 0.f;
    #pragma unroll
    for (int i = 0; i < 4; i++) { float d = v[i]-mean; s2 += d*d; }
    #pragma unroll
    for (int o = 16; o; o >>= 1) s2 += __shfl_xor_sync(0xffffffffu, s2, o);
    __syncthreads();
    if ((tid & 31) == 0) sh[tid >> 5] = s2;
    __syncthreads();
    float tot2 = 0.f;
    #pragma unroll
    for (int i = 0; i < 8; i++) tot2 += sh[i];
    const float inv = 1.f / (sqrtf(tot2 * (1.f/(float)D_MODEL)) + LN_EPS);
    #pragma unroll
    for (int i = 0; i < 4; i++) {
        int c = tid + i*256;
        float r = gamma[c]*(v[i]-mean)*inv + beta[c];
        out[(size_t)row*D_MODEL + c] = r;
        if (EMIT16) o16[(size_t)row*D_MODEL + c] = __float2half_rn(r);
    }
}

// ================= launcher =================
extern "C" void kernel_launch(void* const* d_in, const int* in_sizes, int n_in,
                              void* d_out, int out_size)
{
    const float* x   = (const float*)d_in[0];
    const float* Wq  = (const float*)d_in[1];
    const float* bq  = (const float*)d_in[2];
    const float* Wk  = (const float*)d_in[3];
    const float* bk  = (const float*)d_in[4];
    const float* Wv  = (const float*)d_in[5];
    const float* bv  = (const float*)d_in[6];
    const float* Wo  = (const float*)d_in[7];
    const float* bo  = (const float*)d_in[8];
    const float* W1  = (const float*)d_in[9];
    const float* b1  = (const float*)d_in[10];
    const float* W2  = (const float*)d_in[11];
    const float* b2  = (const float*)d_in[12];
    const float* g1  = (const float*)d_in[13];
    const float* be1 = (const float*)d_in[14];
    const float* g2  = (const float*)d_in[15];
    const float* be2 = (const float*)d_in[16];
    float* out = (float*)d_out;

    float *t1,*h;
    __half *x16,*q16,*k16,*v16,*c16,*h16,*f116,*wqkv16,*wo16,*w116,*w216;
    cudaGetSymbolAddress((void**)&t1,     g_t1);
    cudaGetSymbolAddress((void**)&h,      g_h);
    cudaGetSymbolAddress((void**)&x16,    g_x16);
    cudaGetSymbolAddress((void**)&q16,    g_q16);
    cudaGetSymbolAddress((void**)&k16,    g_k16);
    cudaGetSymbolAddress((void**)&v16,    g_v16);
    cudaGetSymbolAddress((void**)&c16,    g_c16);
    cudaGetSymbolAddress((void**)&h16,    g_h16);
    cudaGetSymbolAddress((void**)&f116,   g_f116);
    cudaGetSymbolAddress((void**)&wqkv16, g_wqkv16);
    cudaGetSymbolAddress((void**)&wo16,   g_wo16);
    cudaGetSymbolAddress((void**)&w116,   g_w116);
    cudaGetSymbolAddress((void**)&w216,   g_w216);

    cudaFuncSetAttribute(gemm_mma<0>, cudaFuncAttributeMaxDynamicSharedMemorySize, GEMM_SMEM);
    cudaFuncSetAttribute(gemm_mma<1>, cudaFuncAttributeMaxDynamicSharedMemorySize, GEMM_SMEM);
    cudaFuncSetAttribute(gemm_mma<3>, cudaFuncAttributeMaxDynamicSharedMemorySize, GEMM_SMEM);
    cudaFuncSetAttribute(attention_mma, cudaFuncAttributeMaxDynamicSharedMemorySize, ATT_SMEM);

    const int nX = NROWS*D_MODEL;
    dim3 tt(32, 8);
    dim3 thr(256);

    cvt_f16_kernel<<<nX/2048, 256>>>(x, x16, nX);
    transpose_all_kernel<<<12288, tt>>>(Wq, Wk, Wv, Wo, W1, W2,
                                        wqkv16, wo16, w116, w216);
    // fused QKV (Q prescaled fp16, K/V fp16)
    gemm_mma<3><<<dim3(24, 32), thr, GEMM_SMEM>>>(x16, wqkv16, bq, bk, bv,
                                                  nullptr, q16, k16, v16, D_MODEL, D_MODEL);
    // attention (4 warps x 32 rows)
    attention_mma<<<dim3(SEQ/128, BATCH*NHEADS), dim3(128), ATT_SMEM>>>(q16, k16, v16, c16);
    // Wo -> t1 (f32)
    gemm_mma<0><<<dim3(8, 32), thr, GEMM_SMEM>>>(c16, wo16, bo, nullptr, nullptr,
                                                 t1, nullptr, nullptr, nullptr, D_MODEL, D_MODEL);
    // LN1 -> h (f32) + h16
    add_ln_kernel<true><<<NROWS, thr>>>(x, t1, g1, be1, h, h16);
    // FF1 (relu -> fp16)
    gemm_mma<1><<<dim3(32, 32), thr, GEMM_SMEM>>>(h16, w116, b1, nullptr, nullptr,
                                                  nullptr, f116, nullptr, nullptr, D_MODEL, D_FF);
    // FF2 -> t1 (f32)
    gemm_mma<0><<<dim3(8, 32), thr, GEMM_SMEM>>>(f116, w216, b2, nullptr, nullptr,
                                                 t1, nullptr, nullptr, nullptr, D_FF, D_MODEL);
    // LN2 -> out
    add_ln_kernel<false><<<NROWS, thr>>>(h, t1, g2, be2, out, nullptr);
}

// round 14
// speedup vs baseline: 1.0193x; 1.0081x over previous
#include <cuda_runtime.h>
#include <cuda_fp16.h>
#include <math.h>
#include <stdint.h>

#define D_MODEL 1024
#define NHEADS  16
#define DKH     64
#define D_FF    4096
#define BATCH   2
#define SEQ     2048
#define NROWS   (BATCH*SEQ)
#define LN_EPS  1e-6f

#define SWZ128(x) ((x) ^ (((x) >> 3) & 0x70))

// ================= PTX helpers ============================================
__device__ __forceinline__ uint32_t smem_u32(const void* p) {
    uint32_t a;
    asm("{ .reg .u64 t; cvta.to.shared.u64 t, %1; cvt.u32.u64 %0, t; }" : "=r"(a) : "l"(p));
    return a;
}
__device__ __forceinline__ void ldsm_x4(uint32_t& r0, uint32_t& r1, uint32_t& r2, uint32_t& r3, uint32_t addr) {
    asm volatile("ldmatrix.sync.aligned.m8n8.x4.shared.b16 {%0,%1,%2,%3}, [%4];"
                 : "=r"(r0), "=r"(r1), "=r"(r2), "=r"(r3) : "r"(addr));
}
__device__ __forceinline__ void ldsm_x4_t(uint32_t& r0, uint32_t& r1, uint32_t& r2, uint32_t& r3, uint32_t addr) {
    asm volatile("ldmatrix.sync.aligned.m8n8.x4.trans.shared.b16 {%0,%1,%2,%3}, [%4];"
                 : "=r"(r0), "=r"(r1), "=r"(r2), "=r"(r3) : "r"(addr));
}
__device__ __forceinline__ void mma_f16(float* c, uint32_t a0, uint32_t a1, uint32_t a2, uint32_t a3,
                                        uint32_t b0, uint32_t b1) {
    asm volatile(
        "mma.sync.aligned.m16n8k16.row.col.f32.f16.f16.f32 "
        "{%0,%1,%2,%3}, {%4,%5,%6,%7}, {%8,%9}, {%0,%1,%2,%3};"
        : "+f"(c[0]), "+f"(c[1]), "+f"(c[2]), "+f"(c[3])
        : "r"(a0), "r"(a1), "r"(a2), "r"(a3), "r"(b0), "r"(b1));
}
__device__ __forceinline__ void cp16(uint32_t saddr, const void* gptr) {
    asm volatile("cp.async.cg.shared.global [%0], [%1], 16;" :: "r"(saddr), "l"(gptr));
}
#define CP_COMMIT() asm volatile("cp.async.commit_group;" ::: "memory")
#define CP_WAIT(n)  asm volatile("cp.async.wait_group %0;" :: "n"(n) : "memory")
__device__ __forceinline__ float ex2f(float x) { float y; asm("ex2.approx.f32 %0, %1;" : "=f"(y) : "f"(x)); return y; }
__device__ __forceinline__ uint32_t h2ex2(uint32_t x) {
    uint32_t y; asm("ex2.approx.f16x2 %0, %1;" : "=r"(y) : "r"(x)); return y;
}
__device__ __forceinline__ uint32_t pack_h2(float a, float b) {
    __half2 h = __floats2half2_rn(a, b);
    return *(uint32_t*)&h;
}

// ================= scratch =================
__device__ float g_t1[(size_t)NROWS*D_MODEL];
__device__ float g_h [(size_t)NROWS*D_MODEL];

__device__ __half g_x16 [(size_t)NROWS*D_MODEL];
__device__ __half g_q16 [(size_t)NROWS*D_MODEL];
__device__ __half g_k16 [(size_t)NROWS*D_MODEL];
__device__ __half g_v16 [(size_t)NROWS*D_MODEL];
__device__ __half g_c16 [(size_t)NROWS*D_MODEL];
__device__ __half g_h16 [(size_t)NROWS*D_MODEL];
__device__ __half g_f116[(size_t)NROWS*D_FF];
__device__ __half g_wqkv16[(size_t)3*D_MODEL*D_MODEL];
__device__ __half g_wo16 [(size_t)D_MODEL*D_MODEL];
__device__ __half g_w116 [(size_t)D_FF*D_MODEL];
__device__ __half g_w216 [(size_t)D_MODEL*D_FF];

// ================= conversion kernels =================
// 16 elems/thread: 4 float4 loads (MLP 4+), 2 uint4 stores
__global__ __launch_bounds__(256)
void cvt_f16_kernel(const float* __restrict__ in, __half* __restrict__ out, int n)
{
    int i = (blockIdx.x * 256 + threadIdx.x) * 16;
    if (i >= n) return;
    float4 v0 = *(const float4*)(in + i);
    float4 v1 = *(const float4*)(in + i + 4);
    float4 v2 = *(const float4*)(in + i + 8);
    float4 v3 = *(const float4*)(in + i + 12);
    uint4 o0, o1;
    o0.x = pack_h2(v0.x, v0.y); o0.y = pack_h2(v0.z, v0.w);
    o0.z = pack_h2(v1.x, v1.y); o0.w = pack_h2(v1.z, v1.w);
    o1.x = pack_h2(v2.x, v2.y); o1.y = pack_h2(v2.z, v2.w);
    o1.z = pack_h2(v3.x, v3.y); o1.w = pack_h2(v3.z, v3.w);
    *(uint4*)(out + i)     = o0;
    *(uint4*)(out + i + 8) = o1;
}

// 64x64-tile transpose: float4 loads, uint4 (8-half) stores along k.
// 3072 blocks: [0,1024) Wq/Wk/Wv/Wo (256 tiles each, K=M=1024),
//              [1024,2048) W1 (K=1024,M=4096), [2048,3072) W2 (K=4096,M=1024)
__global__ __launch_bounds__(256)
void transpose_all_kernel(const float* __restrict__ Wq, const float* __restrict__ Wk,
                          const float* __restrict__ Wv, const float* __restrict__ Wo,
                          const float* __restrict__ W1, const float* __restrict__ W2,
                          __half* __restrict__ wqkv, __half* __restrict__ wo,
                          __half* __restrict__ w1,   __half* __restrict__ w2)
{
    __shared__ float ts[64][65];
    const int id = blockIdx.x;
    const float* W; __half* T;
    int K, M, rowoff, bx, by;
    if (id < 1024) {
        int mat = id >> 8, r = id & 255;
        bx = r & 15; by = r >> 4;
        K = 1024; M = 1024;
        if      (mat == 0) { W = Wq; T = wqkv; rowoff = 0;    }
        else if (mat == 1) { W = Wk; T = wqkv; rowoff = 1024; }
        else if (mat == 2) { W = Wv; T = wqkv; rowoff = 2048; }
        else               { W = Wo; T = wo;   rowoff = 0;    }
    } else if (id < 2048) {
        int r = id - 1024;
        bx = r & 63; by = r >> 6;
        K = 1024; M = 4096; W = W1; T = w1; rowoff = 0;
    } else {
        int r = id - 2048;
        bx = r & 15; by = r >> 4;
        K = 4096; M = 1024; W = W2; T = w2; rowoff = 0;
    }
    const int m0 = bx * 64, k0 = by * 64;
    const int tid = threadIdx.x;

    // load 64x64 f32 tile: 16 float4-cols x 16 k-rows per pass, 4 passes
    const int c4 = tid & 15;          // float4 column 0..15
    const int kr = tid >> 4;          // 0..15
    #pragma unroll
    for (int i = 0; i < 4; i++) {
        int k = kr + i*16;
        float4 v = *(const float4*)(W + (size_t)(k0+k)*M + m0 + c4*4);
        ts[k][c4*4+0] = v.x; ts[k][c4*4+1] = v.y;
        ts[k][c4*4+2] = v.z; ts[k][c4*4+3] = v.w;
    }
    __syncthreads();

    // store transposed: per thread 8 contiguous halves along k (uint4)
    const int seg = tid & 7;          // k-segment 0..7 (8 halves each)
    const int mb  = tid >> 3;         // 0..31
    #pragma unroll
    for (int j = 0; j < 2; j++) {
        int m = mb + j*32;
        uint4 o;
        o.x = pack_h2(ts[seg*8+0][m], ts[seg*8+1][m]);
        o.y = pack_h2(ts[seg*8+2][m], ts[seg*8+3][m]);
        o.z = pack_h2(ts[seg*8+4][m], ts[seg*8+5][m]);
        o.w = pack_h2(ts[seg*8+6][m], ts[seg*8+7][m]);
        *(uint4*)(T + (size_t)(rowoff + m0 + m)*K + k0 + seg*8) = o;
    }
}

// ================= mma.sync fp16 GEMM (3-stage pipeline) ===================
#define GEMM_SMEM (3*32768)

template<int MODE>
__global__ __launch_bounds__(256, 2)
void gemm_mma(const __half* __restrict__ A16, const __half* __restrict__ B16,
              const float* __restrict__ bias, const float* __restrict__ bias2,
              const float* __restrict__ bias3,
              float* __restrict__ Cf,
              __half* __restrict__ C0, __half* __restrict__ C1, __half* __restrict__ C2,
              int K, int M)
{
    extern __shared__ char sb[];
    const int tid  = threadIdx.x;
    const int wid  = tid >> 5;
    const int lane = tid & 31;
    const int wm   = wid >> 2;
    const int wn   = wid & 3;
    const int brow = blockIdx.y * 128;
    const int bcol = blockIdx.x * 128;
    const uint32_t sbu = smem_u32(sb);

    float acc[4][4][4];
    #pragma unroll
    for (int mf = 0; mf < 4; mf++)
      #pragma unroll
      for (int nf = 0; nf < 4; nf++)
        #pragma unroll
        for (int q = 0; q < 4; q++) acc[mf][nf][q] = 0.f;

    const int NC = K >> 6;
    const __half* srcs[2] = {A16, B16};
    const int bases[2] = {brow, bcol};

    auto prefetch = [&](int c) {
        const int kc = c << 6;
        const uint32_t boff = (uint32_t)(c % 3) * 32768u;
        #pragma unroll
        for (int it = 0; it < 8; it++) {
            int idx  = tid + it*256;
            int tile = idx >> 10;
            int rem  = idx & 1023;
            int r    = rem >> 3;
            int chn  = rem & 7;
            const __half* g = srcs[tile] + (size_t)(bases[tile] + r)*K + kc + chn*8;
            cp16(sbu + boff + (uint32_t)tile*16384u + SWZ128((uint32_t)((r << 7) + (chn << 4))), g);
        }
        CP_COMMIT();
    };

    prefetch(0);
    prefetch(1);

    const int rloc   = (lane & 7) + ((lane >> 3) & 1) * 8;
    const int kpiece = (lane >> 4) << 4;

    for (int c = 0; c < NC; c++) {
        if (c + 1 < NC) CP_WAIT(1); else CP_WAIT(0);
        __syncthreads();
        if (c + 2 < NC) prefetch(c + 2);

        const uint32_t buf = sbu + (uint32_t)(c % 3) * 32768u;
        const uint32_t aB  = buf;
        const uint32_t bB  = buf + 16384u;

        #pragma unroll
        for (int ks = 0; ks < 4; ks++) {
            const uint32_t wb = (uint32_t)(ks*32 + kpiece);
            uint32_t af[4][4];
            #pragma unroll
            for (int mf = 0; mf < 4; mf++) {
                uint32_t off = SWZ128((uint32_t)(((wm*64 + mf*16 + rloc) << 7)) + wb);
                ldsm_x4(af[mf][0], af[mf][1], af[mf][2], af[mf][3], aB + off);
            }
            uint32_t bf[2][4];
            #pragma unroll
            for (int g = 0; g < 2; g++) {
                uint32_t off = SWZ128((uint32_t)(((wn*32 + g*16 + rloc) << 7)) + wb);
                ldsm_x4(bf[g][0], bf[g][1], bf[g][2], bf[g][3], bB + off);
            }
            #pragma unroll
            for (int mf = 0; mf < 4; mf++) {
                #pragma unroll
                for (int g = 0; g < 2; g++) {
                    mma_f16(acc[mf][g*2],   af[mf][0], af[mf][1], af[mf][2], af[mf][3], bf[g][0], bf[g][2]);
                    mma_f16(acc[mf][g*2+1], af[mf][0], af[mf][1], af[mf][2], af[mf][3], bf[g][1], bf[g][3]);
                }
            }
        }
    }

    const int qr = lane >> 2;
    const int qc = (lane & 3) * 2;

    int sec = 0;
    const float* bi = bias;
    __half* Dh = C0;
    int ostride = M;
    float oscale = 1.f;
    if (MODE == 3) {
        sec = bcol >> 10;
        bi  = (sec == 0) ? bias : (sec == 1 ? bias2 : bias3);
        Dh  = (sec == 0) ? C0 : (sec == 1 ? C1 : C2);
        ostride = D_MODEL;
        if (sec == 0) oscale = 0.125f * 1.44269504f;
    }

    #pragma unroll
    for (int mf = 0; mf < 4; mf++) {
        #pragma unroll
        for (int nf = 0; nf < 4; nf++) {
            const int row  = brow + wm*64 + mf*16 + qr;
            const int col  = bcol + wn*32 + nf*8 + qc;
            const int colS = (MODE == 3) ? (col & 1023) : col;
            const float b0 = __ldg(bi + colS), b1 = __ldg(bi + colS + 1);
            float v00 = acc[mf][nf][0] + b0, v01 = acc[mf][nf][1] + b1;
            float v10 = acc[mf][nf][2] + b0, v11 = acc[mf][nf][3] + b1;
            if (MODE == 0) {
                *(float2*)(Cf + (size_t)row*M + colS)     = make_float2(v00, v01);
                *(float2*)(Cf + (size_t)(row+8)*M + colS) = make_float2(v10, v11);
            } else {
                if (MODE == 1) {
                    v00 = fmaxf(v00, 0.f); v01 = fmaxf(v01, 0.f);
                    v10 = fmaxf(v10, 0.f); v11 = fmaxf(v11, 0.f);
                }
                if (MODE == 3) {
                    v00 *= oscale; v01 *= oscale; v10 *= oscale; v11 *= oscale;
                }
                *(uint32_t*)(Dh + (size_t)row*ostride + colS)     = pack_h2(v00, v01);
                *(uint32_t*)(Dh + (size_t)(row+8)*ostride + colS) = pack_h2(v10, v11);
            }
        }
    }
}

// ================= mma.sync fp16 flash attention (R13 config) ==============
#define ATT_SMEM (16384 + 3*16384)
#define ONES_H2 0x3C003C00u

__global__ __launch_bounds__(128, 2)
void attention_mma(const __half* __restrict__ Q16,
                   const __half* __restrict__ K16, const __half* __restrict__ V16,
                   __half* __restrict__ ctx16)
{
    extern __shared__ char sb[];
    const uint32_t sbu = smem_u32(sb);
    const int tid  = threadIdx.x;
    const int wid  = tid >> 5;
    const int lane = tid & 31;
    const int bh   = blockIdx.y;
    const int b    = bh >> 4;
    const int hh   = bh & 15;
    const int q0   = blockIdx.x * 128;
    const size_t rbase = (size_t)b*SEQ*D_MODEL + (size_t)hh*DKH;

    const __half* kvsrc[2] = {K16, V16};
    const int NT = SEQ / 64;

    auto prefetch_kv = [&](int t) {
        const int s0 = t * 64;
        const uint32_t boff = 16384u + (uint32_t)(t % 3) * 16384u;
        #pragma unroll
        for (int it = 0; it < 8; it++) {
            int idx  = tid + it*128;
            int tile = idx >> 9;
            int rem  = idx & 511;
            int r    = rem >> 3;
            int chn  = rem & 7;
            const __half* g = kvsrc[tile] + rbase + (size_t)(s0+r)*D_MODEL + chn*8;
            cp16(sbu + boff + (uint32_t)tile*8192u + SWZ128((uint32_t)((r << 7) + (chn << 4))), g);
        }
        CP_COMMIT();
    };

    {
        #pragma unroll
        for (int it = 0; it < 8; it++) {
            int idx = tid + it*128;
            int r   = idx >> 3;
            int chn = idx & 7;
            const __half* g = Q16 + rbase + (size_t)(q0 + r)*D_MODEL + chn*8;
            cp16(sbu + SWZ128((uint32_t)((r << 7) + (chn << 4))), g);
        }
        CP_COMMIT();
    }
    prefetch_kv(0);
    prefetch_kv(1);

    const int rloc   = (lane & 7) + ((lane >> 3) & 1) * 8;
    const int kpiece = (lane >> 4) << 4;

    CP_WAIT(2);
    __syncthreads();
    uint32_t qf[2][4][4];
    #pragma unroll
    for (int mfr = 0; mfr < 2; mfr++) {
        #pragma unroll
        for (int ks = 0; ks < 4; ks++) {
            uint32_t off = SWZ128((uint32_t)(((wid*32 + mfr*16 + rloc) << 7) + ks*32 + kpiece));
            ldsm_x4(qf[mfr][ks][0], qf[mfr][ks][1], qf[mfr][ks][2], qf[mfr][ks][3], sbu + off);
        }
    }

    float O[2][8][4];
    #pragma unroll
    for (int mfr = 0; mfr < 2; mfr++)
      #pragma unroll
      for (int nt = 0; nt < 8; nt++)
        #pragma unroll
        for (int q = 0; q < 4; q++) O[mfr][nt][q] = 0.f;
    float mr[2][2] = {{-1e30f,-1e30f},{-1e30f,-1e30f}};
    float lr[2][2] = {{0.f,0.f},{0.f,0.f}};

    for (int t = 0; t < NT; t++) {
        if (t + 1 < NT) CP_WAIT(1); else CP_WAIT(0);
        __syncthreads();
        if (t + 2 < NT) prefetch_kv(t + 2);

        const uint32_t kb = sbu + 16384u + (uint32_t)(t % 3) * 16384u;
        const uint32_t vb = kb + 8192u;

        float sc[2][8][4];
        #pragma unroll
        for (int mfr = 0; mfr < 2; mfr++)
          #pragma unroll
          for (int nt = 0; nt < 8; nt++)
            #pragma unroll
            for (int q = 0; q < 4; q++) sc[mfr][nt][q] = 0.f;

        #pragma unroll
        for (int ks = 0; ks < 4; ks++) {
            #pragma unroll
            for (int g = 0; g < 4; g++) {
                uint32_t kf[4];
                uint32_t off = SWZ128((uint32_t)(((g*16 + rloc) << 7) + ks*32 + kpiece));
                ldsm_x4(kf[0], kf[1], kf[2], kf[3], kb + off);
                #pragma unroll
                for (int mfr = 0; mfr < 2; mfr++) {
                    mma_f16(sc[mfr][g*2],   qf[mfr][ks][0], qf[mfr][ks][1], qf[mfr][ks][2], qf[mfr][ks][3], kf[0], kf[2]);
                    mma_f16(sc[mfr][g*2+1], qf[mfr][ks][0], qf[mfr][ks][1], qf[mfr][ks][2], qf[mfr][ks][3], kf[1], kf[3]);
                }
            }
        }

        uint32_t pl[2][8], ph[2][8];
        #pragma unroll
        for (int mfr = 0; mfr < 2; mfr++) {
            float mx0 = -1e30f, mx1 = -1e30f;
            #pragma unroll
            for (int nt = 0; nt < 8; nt++) {
                mx0 = fmaxf(mx0, fmaxf(sc[mfr][nt][0], sc[mfr][nt][1]));
                mx1 = fmaxf(mx1, fmaxf(sc[mfr][nt][2], sc[mfr][nt][3]));
            }
            mx0 = fmaxf(mx0, __shfl_xor_sync(0xffffffffu, mx0, 1));
            mx0 = fmaxf(mx0, __shfl_xor_sync(0xffffffffu, mx0, 2));
            mx1 = fmaxf(mx1, __shfl_xor_sync(0xffffffffu, mx1, 1));
            mx1 = fmaxf(mx1, __shfl_xor_sync(0xffffffffu, mx1, 2));
            const float mn0 = fmaxf(mr[mfr][0], mx0), mn1 = fmaxf(mr[mfr][1], mx1);
            const float a0 = ex2f(mr[mfr][0] - mn0), a1 = ex2f(mr[mfr][1] - mn1);

            #pragma unroll
            for (int nt = 0; nt < 8; nt++) {
                pl[mfr][nt] = h2ex2(pack_h2(sc[mfr][nt][0] - mn0, sc[mfr][nt][1] - mn0));
                ph[mfr][nt] = h2ex2(pack_h2(sc[mfr][nt][2] - mn1, sc[mfr][nt][3] - mn1));
            }

            float sacc[4] = {0.f, 0.f, 0.f, 0.f};
            #pragma unroll
            for (int ks = 0; ks < 4; ks++)
                mma_f16(sacc, pl[mfr][2*ks], ph[mfr][2*ks], pl[mfr][2*ks+1], ph[mfr][2*ks+1], ONES_H2, ONES_H2);

            lr[mfr][0] = lr[mfr][0]*a0 + sacc[0];
            lr[mfr][1] = lr[mfr][1]*a1 + sacc[2];
            mr[mfr][0] = mn0; mr[mfr][1] = mn1;
            #pragma unroll
            for (int nt = 0; nt < 8; nt++) {
                O[mfr][nt][0] *= a0; O[mfr][nt][1] *= a0;
                O[mfr][nt][2] *= a1; O[mfr][nt][3] *= a1;
            }
        }

        #pragma unroll
        for (int ks = 0; ks < 4; ks++) {
            const int e = 2*ks, o = 2*ks + 1;
            #pragma unroll
            for (int dg = 0; dg < 4; dg++) {
                uint32_t vf[4];
                uint32_t off = SWZ128((uint32_t)(((ks*16 + rloc) << 7) + dg*32 + kpiece));
                ldsm_x4_t(vf[0], vf[1], vf[2], vf[3], vb + off);
                #pragma unroll
                for (int mfr = 0; mfr < 2; mfr++) {
                    mma_f16(O[mfr][dg*2],   pl[mfr][e], ph[mfr][e], pl[mfr][o], ph[mfr][o], vf[0], vf[1]);
                    mma_f16(O[mfr][dg*2+1], pl[mfr][e], ph[mfr][e], pl[mfr][o], ph[mfr][o], vf[2], vf[3]);
                }
            }
        }
    }

    const int qr = lane >> 2;
    const int qc = (lane & 3) * 2;
    #pragma unroll
    for (int mfr = 0; mfr < 2; mfr++) {
        const float i0 = 1.f / lr[mfr][0], i1 = 1.f / lr[mfr][1];
        const int rowA = q0 + wid*32 + mfr*16 + qr;
        #pragma unroll
        for (int nt = 0; nt < 8; nt++) {
            float v0 = O[mfr][nt][0]*i0, v1 = O[mfr][nt][1]*i0;
            float v2 = O[mfr][nt][2]*i1, v3 = O[mfr][nt][3]*i1;
            size_t oA = rbase + (size_t)rowA*D_MODEL + nt*8 + qc;
            size_t oB = oA + 8*D_MODEL;
            *(uint32_t*)(ctx16 + oA) = pack_h2(v0, v1);
            *(uint32_t*)(ctx16 + oB) = pack_h2(v2, v3);
        }
    }
}

// ================= residual add + LayerNorm (float4 vectorized) ============
template<bool EMIT16>
__global__ __launch_bounds__(256)
void add_ln_kernel(const float* __restrict__ A, const float* __restrict__ Bm,
                   const float* __restrict__ gamma, const float* __restrict__ beta,
                   float* __restrict__ out, __half* __restrict__ o16)
{
    __shared__ float sh[8];
    const int row = blockIdx.x;
    const int tid = threadIdx.x;
    const int c   = tid * 4;
    const float* a  = A  + (size_t)row*D_MODEL;
    const float* bb = Bm + (size_t)row*D_MODEL;
    float4 va = *(const float4*)(a + c);
    float4 vb = *(const float4*)(bb + c);
    float v[4] = {va.x+vb.x, va.y+vb.y, va.z+vb.z, va.w+vb.w};
    float s = v[0]+v[1]+v[2]+v[3];
    #pragma unroll
    for (int o = 16; o; o >>= 1) s += __shfl_xor_sync(0xffffffffu, s, o);
    if ((tid & 31) == 0) sh[tid >> 5] = s;
    __syncthreads();
    float tot = 0.f;
    #pragma unroll
    for (int i = 0; i < 8; i++) tot += sh[i];
    const float mean = tot * (1.f/(float)D_MODEL);
    float s2 = 0.f;
    #pragma unroll
    for (int i = 0; i < 4; i++) { float d = v[i]-mean; s2 += d*d; }
    #pragma unroll
    for (int o = 16; o; o >>= 1) s2 += __shfl_xor_sync(0xffffffffu, s2, o);
    __syncthreads();
    if ((tid & 31) == 0) sh[tid >> 5] = s2;
    __syncthreads();
    float tot2 = 0.f;
    #pragma unroll
    for (int i = 0; i < 8; i++) tot2 += sh[i];
    const float inv = 1.f / (sqrtf(tot2 * (1.f/(float)D_MODEL)) + LN_EPS);
    float4 vg = *(const float4*)(gamma + c);
    float4 ve = *(const float4*)(beta + c);
    float r0 = vg.x*(v[0]-mean)*inv + ve.x;
    float r1 = vg.y*(v[1]-mean)*inv + ve.y;
    float r2 = vg.z*(v[2]-mean)*inv + ve.z;
    float r3 = vg.w*(v[3]-mean)*inv + ve.w;
    *(float4*)(out + (size_t)row*D_MODEL + c) = make_float4(r0, r1, r2, r3);
    if (EMIT16) {
        uint2 o2;
        o2.x = pack_h2(r0, r1);
        o2.y = pack_h2(r2, r3);
        *(uint2*)(o16 + (size_t)row*D_MODEL + c) = o2;
    }
}

// ================= launcher =================
extern "C" void kernel_launch(void* const* d_in, const int* in_sizes, int n_in,
                              void* d_out, int out_size)
{
    const float* x   = (const float*)d_in[0];
    const float* Wq  = (const float*)d_in[1];
    const float* bq  = (const float*)d_in[2];
    const float* Wk  = (const float*)d_in[3];
    const float* bk  = (const float*)d_in[4];
    const float* Wv  = (const float*)d_in[5];
    const float* bv  = (const float*)d_in[6];
    const float* Wo  = (const float*)d_in[7];
    const float* bo  = (const float*)d_in[8];
    const float* W1  = (const float*)d_in[9];
    const float* b1  = (const float*)d_in[10];
    const float* W2  = (const float*)d_in[11];
    const float* b2  = (const float*)d_in[12];
    const float* g1  = (const float*)d_in[13];
    const float* be1 = (const float*)d_in[14];
    const float* g2  = (const float*)d_in[15];
    const float* be2 = (const float*)d_in[16];
    float* out = (float*)d_out;

    float *t1,*h;
    __half *x16,*q16,*k16,*v16,*c16,*h16,*f116,*wqkv16,*wo16,*w116,*w216;
    cudaGetSymbolAddress((void**)&t1,     g_t1);
    cudaGetSymbolAddress((void**)&h,      g_h);
    cudaGetSymbolAddress((void**)&x16,    g_x16);
    cudaGetSymbolAddress((void**)&q16,    g_q16);
    cudaGetSymbolAddress((void**)&k16,    g_k16);
    cudaGetSymbolAddress((void**)&v16,    g_v16);
    cudaGetSymbolAddress((void**)&c16,    g_c16);
    cudaGetSymbolAddress((void**)&h16,    g_h16);
    cudaGetSymbolAddress((void**)&f116,   g_f116);
    cudaGetSymbolAddress((void**)&wqkv16, g_wqkv16);
    cudaGetSymbolAddress((void**)&wo16,   g_wo16);
    cudaGetSymbolAddress((void**)&w116,   g_w116);
    cudaGetSymbolAddress((void**)&w216,   g_w216);

    cudaFuncSetAttribute(gemm_mma<0>, cudaFuncAttributeMaxDynamicSharedMemorySize, GEMM_SMEM);
    cudaFuncSetAttribute(gemm_mma<1>, cudaFuncAttributeMaxDynamicSharedMemorySize, GEMM_SMEM);
    cudaFuncSetAttribute(gemm_mma<3>, cudaFuncAttributeMaxDynamicSharedMemorySize, GEMM_SMEM);
    cudaFuncSetAttribute(attention_mma, cudaFuncAttributeMaxDynamicSharedMemorySize, ATT_SMEM);

    const int nX = NROWS*D_MODEL;
    dim3 thr(256);

    cvt_f16_kernel<<<nX/4096, 256>>>(x, x16, nX);
    transpose_all_kernel<<<3072, 256>>>(Wq, Wk, Wv, Wo, W1, W2,
                                        wqkv16, wo16, w116, w216);
    // fused QKV (Q prescaled fp16, K/V fp16)
    gemm_mma<3><<<dim3(24, 32), thr, GEMM_SMEM>>>(x16, wqkv16, bq, bk, bv,
                                                  nullptr, q16, k16, v16, D_MODEL, D_MODEL);
    // attention (4 warps x 32 rows)
    attention_mma<<<dim3(SEQ/128, BATCH*NHEADS), dim3(128), ATT_SMEM>>>(q16, k16, v16, c16);
    // Wo -> t1 (f32)
    gemm_mma<0><<<dim3(8, 32), thr, GEMM_SMEM>>>(c16, wo16, bo, nullptr, nullptr,
                                                 t1, nullptr, nullptr, nullptr, D_MODEL, D_MODEL);
    // LN1 -> h (f32) + h16
    add_ln_kernel<true><<<NROWS, thr>>>(x, t1, g1, be1, h, h16);
    // FF1 (relu -> fp16)
    gemm_mma<1><<<dim3(32, 32), thr, GEMM_SMEM>>>(h16, w116, b1, nullptr, nullptr,
                                                  nullptr, f116, nullptr, nullptr, D_MODEL, D_FF);
    // FF2 -> t1 (f32)
    gemm_mma<0><<<dim3(8, 32), thr, GEMM_SMEM>>>(f116, w216, b2, nullptr, nullptr,
                                                 t1, nullptr, nullptr, nullptr, D_FF, D_MODEL);
    // LN2 -> out
    add_ln_kernel<false><<<NROWS, thr>>>(h, t1, g2, be2, out, nullptr);
}

// round 16
// speedup vs baseline: 1.0372x; 1.0176x over previous
#include <cuda_runtime.h>
#include <cuda_fp16.h>
#include <math.h>
#include <stdint.h>

#define D_MODEL 1024
#define NHEADS  16
#define DKH     64
#define D_FF    4096
#define BATCH   2
#define SEQ     2048
#define NROWS   (BATCH*SEQ)
#define LN_EPS  1e-6f

#define SWZ128(x) ((x) ^ (((x) >> 3) & 0x70))

// ================= PTX helpers ============================================
__device__ __forceinline__ uint32_t smem_u32(const void* p) {
    uint32_t a;
    asm("{ .reg .u64 t; cvta.to.shared.u64 t, %1; cvt.u32.u64 %0, t; }" : "=r"(a) : "l"(p));
    return a;
}
__device__ __forceinline__ void ldsm_x4(uint32_t& r0, uint32_t& r1, uint32_t& r2, uint32_t& r3, uint32_t addr) {
    asm volatile("ldmatrix.sync.aligned.m8n8.x4.shared.b16 {%0,%1,%2,%3}, [%4];"
                 : "=r"(r0), "=r"(r1), "=r"(r2), "=r"(r3) : "r"(addr));
}
__device__ __forceinline__ void ldsm_x4_t(uint32_t& r0, uint32_t& r1, uint32_t& r2, uint32_t& r3, uint32_t addr) {
    asm volatile("ldmatrix.sync.aligned.m8n8.x4.trans.shared.b16 {%0,%1,%2,%3}, [%4];"
                 : "=r"(r0), "=r"(r1), "=r"(r2), "=r"(r3) : "r"(addr));
}
__device__ __forceinline__ void mma_f16(float* c, uint32_t a0, uint32_t a1, uint32_t a2, uint32_t a3,
                                        uint32_t b0, uint32_t b1) {
    asm volatile(
        "mma.sync.aligned.m16n8k16.row.col.f32.f16.f16.f32 "
        "{%0,%1,%2,%3}, {%4,%5,%6,%7}, {%8,%9}, {%0,%1,%2,%3};"
        : "+f"(c[0]), "+f"(c[1]), "+f"(c[2]), "+f"(c[3])
        : "r"(a0), "r"(a1), "r"(a2), "r"(a3), "r"(b0), "r"(b1));
}
__device__ __forceinline__ void cp16(uint32_t saddr, const void* gptr) {
    asm volatile("cp.async.cg.shared.global [%0], [%1], 16;" :: "r"(saddr), "l"(gptr));
}
#define CP_COMMIT() asm volatile("cp.async.commit_group;" ::: "memory")
#define CP_WAIT(n)  asm volatile("cp.async.wait_group %0;" :: "n"(n) : "memory")
__device__ __forceinline__ float ex2f(float x) { float y; asm("ex2.approx.f32 %0, %1;" : "=f"(y) : "f"(x)); return y; }
__device__ __forceinline__ uint32_t h2ex2(uint32_t x) {
    uint32_t y; asm("ex2.approx.f16x2 %0, %1;" : "=r"(y) : "r"(x)); return y;
}
__device__ __forceinline__ uint32_t pack_h2(float a, float b) {
    __half2 h = __floats2half2_rn(a, b);
    return *(uint32_t*)&h;
}

// ================= scratch =================
__device__ float g_t1[(size_t)NROWS*D_MODEL];
__device__ float g_h [(size_t)NROWS*D_MODEL];

__device__ __half g_x16 [(size_t)NROWS*D_MODEL];
__device__ __half g_q16 [(size_t)NROWS*D_MODEL];
__device__ __half g_k16 [(size_t)NROWS*D_MODEL];
__device__ __half g_v16 [(size_t)NROWS*D_MODEL];
__device__ __half g_c16 [(size_t)NROWS*D_MODEL];
__device__ __half g_h16 [(size_t)NROWS*D_MODEL];
__device__ __half g_f116[(size_t)NROWS*D_FF];
__device__ __half g_wqkv16[(size_t)3*D_MODEL*D_MODEL];
__device__ __half g_wo16 [(size_t)D_MODEL*D_MODEL];
__device__ __half g_w116 [(size_t)D_FF*D_MODEL];
__device__ __half g_w216 [(size_t)D_MODEL*D_FF];

// ================= conversion kernels =================
__global__ __launch_bounds__(256)
void cvt_f16_kernel(const float* __restrict__ in, __half* __restrict__ out, int n)
{
    int i = (blockIdx.x * 256 + threadIdx.x) * 16;
    if (i >= n) return;
    float4 v0 = *(const float4*)(in + i);
    float4 v1 = *(const float4*)(in + i + 4);
    float4 v2 = *(const float4*)(in + i + 8);
    float4 v3 = *(const float4*)(in + i + 12);
    uint4 o0, o1;
    o0.x = pack_h2(v0.x, v0.y); o0.y = pack_h2(v0.z, v0.w);
    o0.z = pack_h2(v1.x, v1.y); o0.w = pack_h2(v1.z, v1.w);
    o1.x = pack_h2(v2.x, v2.y); o1.y = pack_h2(v2.z, v2.w);
    o1.z = pack_h2(v3.x, v3.y); o1.w = pack_h2(v3.z, v3.w);
    *(uint4*)(out + i)     = o0;
    *(uint4*)(out + i + 8) = o1;
}

// 64x64-tile transpose: float4 loads, uint4 stores along k. 3072 blocks.
__global__ __launch_bounds__(256)
void transpose_all_kernel(const float* __restrict__ Wq, const float* __restrict__ Wk,
                          const float* __restrict__ Wv, const float* __restrict__ Wo,
                          const float* __restrict__ W1, const float* __restrict__ W2,
                          __half* __restrict__ wqkv, __half* __restrict__ wo,
                          __half* __restrict__ w1,   __half* __restrict__ w2)
{
    __shared__ float ts[64][65];
    const int id = blockIdx.x;
    const float* W; __half* T;
    int K, M, rowoff, bx, by;
    if (id < 1024) {
        int mat = id >> 8, r = id & 255;
        bx = r & 15; by = r >> 4;
        K = 1024; M = 1024;
        if      (mat == 0) { W = Wq; T = wqkv; rowoff = 0;    }
        else if (mat == 1) { W = Wk; T = wqkv; rowoff = 1024; }
        else if (mat == 2) { W = Wv; T = wqkv; rowoff = 2048; }
        else               { W = Wo; T = wo;   rowoff = 0;    }
    } else if (id < 2048) {
        int r = id - 1024;
        bx = r & 63; by = r >> 6;
        K = 1024; M = 4096; W = W1; T = w1; rowoff = 0;
    } else {
        int r = id - 2048;
        bx = r & 15; by = r >> 4;
        K = 4096; M = 1024; W = W2; T = w2; rowoff = 0;
    }
    const int m0 = bx * 64, k0 = by * 64;
    const int tid = threadIdx.x;

    const int c4 = tid & 15;
    const int kr = tid >> 4;
    #pragma unroll
    for (int i = 0; i < 4; i++) {
        int k = kr + i*16;
        float4 v = *(const float4*)(W + (size_t)(k0+k)*M + m0 + c4*4);
        ts[k][c4*4+0] = v.x; ts[k][c4*4+1] = v.y;
        ts[k][c4*4+2] = v.z; ts[k][c4*4+3] = v.w;
    }
    __syncthreads();

    const int seg = tid & 7;
    const int mb  = tid >> 3;
    #pragma unroll
    for (int j = 0; j < 2; j++) {
        int m = mb + j*32;
        uint4 o;
        o.x = pack_h2(ts[seg*8+0][m], ts[seg*8+1][m]);
        o.y = pack_h2(ts[seg*8+2][m], ts[seg*8+3][m]);
        o.z = pack_h2(ts[seg*8+4][m], ts[seg*8+5][m]);
        o.w = pack_h2(ts[seg*8+6][m], ts[seg*8+7][m]);
        *(uint4*)(T + (size_t)(rowoff + m0 + m)*K + k0 + seg*8) = o;
    }
}

// ================= mma.sync fp16 GEMM (4 warps x 64x64 tiles) ==============
// 128 threads. Warp (wm,wn) owns 64x64 of the 128x128 CTA tile.
// Per ks: 4 A-ldsm + 4 B-ldsm -> 32 MMAs (ratio 4:1, was 1.33).
#define GEMM_SMEM (3*32768)

template<int MODE>
__global__ __launch_bounds__(128, 2)
void gemm_mma(const __half* __restrict__ A16, const __half* __restrict__ B16,
              const float* __restrict__ bias, const float* __restrict__ bias2,
              const float* __restrict__ bias3,
              float* __restrict__ Cf,
              __half* __restrict__ C0, __half* __restrict__ C1, __half* __restrict__ C2,
              int K, int M)
{
    extern __shared__ char sb[];
    const int tid  = threadIdx.x;
    const int wid  = tid >> 5;
    const int lane = tid & 31;
    const int wm   = wid >> 1;            // 0..1
    const int wn   = wid & 1;             // 0..1
    const int brow = blockIdx.y * 128;
    const int bcol = blockIdx.x * 128;
    const uint32_t sbu = smem_u32(sb);

    float acc[4][8][4];
    #pragma unroll
    for (int mf = 0; mf < 4; mf++)
      #pragma unroll
      for (int nf = 0; nf < 8; nf++)
        #pragma unroll
        for (int q = 0; q < 4; q++) acc[mf][nf][q] = 0.f;

    const int NC = K >> 6;
    const __half* srcs[2] = {A16, B16};
    const int bases[2] = {brow, bcol};

    auto prefetch = [&](int c) {
        const int kc = c << 6;
        const uint32_t boff = (uint32_t)(c % 3) * 32768u;
        #pragma unroll
        for (int it = 0; it < 16; it++) {
            int idx  = tid + it*128;
            int tile = idx >> 10;
            int rem  = idx & 1023;
            int r    = rem >> 3;
            int chn  = rem & 7;
            const __half* g = srcs[tile] + (size_t)(bases[tile] + r)*K + kc + chn*8;
            cp16(sbu + boff + (uint32_t)tile*16384u + SWZ128((uint32_t)((r << 7) + (chn << 4))), g);
        }
        CP_COMMIT();
    };

    prefetch(0);
    prefetch(1);

    const int rloc   = (lane & 7) + ((lane >> 3) & 1) * 8;
    const int kpiece = (lane >> 4) << 4;

    for (int c = 0; c < NC; c++) {
        if (c + 1 < NC) CP_WAIT(1); else CP_WAIT(0);
        __syncthreads();
        if (c + 2 < NC) prefetch(c + 2);

        const uint32_t buf = sbu + (uint32_t)(c % 3) * 32768u;
        const uint32_t aB  = buf;
        const uint32_t bB  = buf + 16384u;

        #pragma unroll
        for (int ks = 0; ks < 4; ks++) {
            const uint32_t wb = (uint32_t)(ks*32 + kpiece);
            uint32_t af[4][4];
            #pragma unroll
            for (int mf = 0; mf < 4; mf++) {
                uint32_t off = SWZ128((uint32_t)(((wm*64 + mf*16 + rloc) << 7)) + wb);
                ldsm_x4(af[mf][0], af[mf][1], af[mf][2], af[mf][3], aB + off);
            }
            uint32_t bf[4][4];
            #pragma unroll
            for (int g = 0; g < 4; g++) {
                uint32_t off = SWZ128((uint32_t)(((wn*64 + g*16 + rloc) << 7)) + wb);
                ldsm_x4(bf[g][0], bf[g][1], bf[g][2], bf[g][3], bB + off);
            }
            #pragma unroll
            for (int mf = 0; mf < 4; mf++) {
                #pragma unroll
                for (int g = 0; g < 4; g++) {
                    mma_f16(acc[mf][g*2],   af[mf][0], af[mf][1], af[mf][2], af[mf][3], bf[g][0], bf[g][2]);
                    mma_f16(acc[mf][g*2+1], af[mf][0], af[mf][1], af[mf][2], af[mf][3], bf[g][1], bf[g][3]);
                }
            }
        }
    }

    const int qr = lane >> 2;
    const int qc = (lane & 3) * 2;

    int sec = 0;
    const float* bi = bias;
    __half* Dh = C0;
    int ostride = M;
    float oscale = 1.f;
    if (MODE == 3) {
        sec = bcol >> 10;
        bi  = (sec == 0) ? bias : (sec == 1 ? bias2 : bias3);
        Dh  = (sec == 0) ? C0 : (sec == 1 ? C1 : C2);
        ostride = D_MODEL;
        if (sec == 0) oscale = 0.125f * 1.44269504f;
    }

    #pragma unroll
    for (int mf = 0; mf < 4; mf++) {
        #pragma unroll
        for (int nf = 0; nf < 8; nf++) {
            const int row  = brow + wm*64 + mf*16 + qr;
            const int col  = bcol + wn*64 + nf*8 + qc;
            const int colS = (MODE == 3) ? (col & 1023) : col;
            const float b0 = __ldg(bi + colS), b1 = __ldg(bi + colS + 1);
            float v00 = acc[mf][nf][0] + b0, v01 = acc[mf][nf][1] + b1;
            float v10 = acc[mf][nf][2] + b0, v11 = acc[mf][nf][3] + b1;
            if (MODE == 0) {
                *(float2*)(Cf + (size_t)row*M + colS)     = make_float2(v00, v01);
                *(float2*)(Cf + (size_t)(row+8)*M + colS) = make_float2(v10, v11);
            } else {
                if (MODE == 1) {
                    v00 = fmaxf(v00, 0.f); v01 = fmaxf(v01, 0.f);
                    v10 = fmaxf(v10, 0.f); v11 = fmaxf(v11, 0.f);
                }
                if (MODE == 3) {
                    v00 *= oscale; v01 *= oscale; v10 *= oscale; v11 *= oscale;
                }
                *(uint32_t*)(Dh + (size_t)row*ostride + colS)     = pack_h2(v00, v01);
                *(uint32_t*)(Dh + (size_t)(row+8)*ostride + colS) = pack_h2(v10, v11);
            }
        }
    }
}

// ================= mma.sync fp16 flash attention (R13 config) ==============
#define ATT_SMEM (16384 + 3*16384)
#define ONES_H2 0x3C003C00u

__global__ __launch_bounds__(128, 2)
void attention_mma(const __half* __restrict__ Q16,
                   const __half* __restrict__ K16, const __half* __restrict__ V16,
                   __half* __restrict__ ctx16)
{
    extern __shared__ char sb[];
    const uint32_t sbu = smem_u32(sb);
    const int tid  = threadIdx.x;
    const int wid  = tid >> 5;
    const int lane = tid & 31;
    const int bh   = blockIdx.y;
    const int b    = bh >> 4;
    const int hh   = bh & 15;
    const int q0   = blockIdx.x * 128;
    const size_t rbase = (size_t)b*SEQ*D_MODEL + (size_t)hh*DKH;

    const __half* kvsrc[2] = {K16, V16};
    const int NT = SEQ / 64;

    auto prefetch_kv = [&](int t) {
        const int s0 = t * 64;
        const uint32_t boff = 16384u + (uint32_t)(t % 3) * 16384u;
        #pragma unroll
        for (int it = 0; it < 8; it++) {
            int idx  = tid + it*128;
            int tile = idx >> 9;
            int rem  = idx & 511;
            int r    = rem >> 3;
            int chn  = rem & 7;
            const __half* g = kvsrc[tile] + rbase + (size_t)(s0+r)*D_MODEL + chn*8;
            cp16(sbu + boff + (uint32_t)tile*8192u + SWZ128((uint32_t)((r << 7) + (chn << 4))), g);
        }
        CP_COMMIT();
    };

    {
        #pragma unroll
        for (int it = 0; it < 8; it++) {
            int idx = tid + it*128;
            int r   = idx >> 3;
            int chn = idx & 7;
            const __half* g = Q16 + rbase + (size_t)(q0 + r)*D_MODEL + chn*8;
            cp16(sbu + SWZ128((uint32_t)((r << 7) + (chn << 4))), g);
        }
        CP_COMMIT();
    }
    prefetch_kv(0);
    prefetch_kv(1);

    const int rloc   = (lane & 7) + ((lane >> 3) & 1) * 8;
    const int kpiece = (lane >> 4) << 4;

    CP_WAIT(2);
    __syncthreads();
    uint32_t qf[2][4][4];
    #pragma unroll
    for (int mfr = 0; mfr < 2; mfr++) {
        #pragma unroll
        for (int ks = 0; ks < 4; ks++) {
            uint32_t off = SWZ128((uint32_t)(((wid*32 + mfr*16 + rloc) << 7) + ks*32 + kpiece));
            ldsm_x4(qf[mfr][ks][0], qf[mfr][ks][1], qf[mfr][ks][2], qf[mfr][ks][3], sbu + off);
        }
    }

    float O[2][8][4];
    #pragma unroll
    for (int mfr = 0; mfr < 2; mfr++)
      #pragma unroll
      for (int nt = 0; nt < 8; nt++)
        #pragma unroll
        for (int q = 0; q < 4; q++) O[mfr][nt][q] = 0.f;
    float mr[2][2] = {{-1e30f,-1e30f},{-1e30f,-1e30f}};
    float lr[2][2] = {{0.f,0.f},{0.f,0.f}};

    for (int t = 0; t < NT; t++) {
        if (t + 1 < NT) CP_WAIT(1); else CP_WAIT(0);
        __syncthreads();
        if (t + 2 < NT) prefetch_kv(t + 2);

        const uint32_t kb = sbu + 16384u + (uint32_t)(t % 3) * 16384u;
        const uint32_t vb = kb + 8192u;

        float sc[2][8][4];
        #pragma unroll
        for (int mfr = 0; mfr < 2; mfr++)
          #pragma unroll
          for (int nt = 0; nt < 8; nt++)
            #pragma unroll
            for (int q = 0; q < 4; q++) sc[mfr][nt][q] = 0.f;

        #pragma unroll
        for (int ks = 0; ks < 4; ks++) {
            #pragma unroll
            for (int g = 0; g < 4; g++) {
                uint32_t kf[4];
                uint32_t off = SWZ128((uint32_t)(((g*16 + rloc) << 7) + ks*32 + kpiece));
                ldsm_x4(kf[0], kf[1], kf[2], kf[3], kb + off);
                #pragma unroll
                for (int mfr = 0; mfr < 2; mfr++) {
                    mma_f16(sc[mfr][g*2],   qf[mfr][ks][0], qf[mfr][ks][1], qf[mfr][ks][2], qf[mfr][ks][3], kf[0], kf[2]);
                    mma_f16(sc[mfr][g*2+1], qf[mfr][ks][0], qf[mfr][ks][1], qf[mfr][ks][2], qf[mfr][ks][3], kf[1], kf[3]);
                }
            }
        }

        uint32_t pl[2][8], ph[2][8];
        #pragma unroll
        for (int mfr = 0; mfr < 2; mfr++) {
            float mx0 = -1e30f, mx1 = -1e30f;
            #pragma unroll
            for (int nt = 0; nt < 8; nt++) {
                mx0 = fmaxf(mx0, fmaxf(sc[mfr][nt][0], sc[mfr][nt][1]));
                mx1 = fmaxf(mx1, fmaxf(sc[mfr][nt][2], sc[mfr][nt][3]));
            }
            mx0 = fmaxf(mx0, __shfl_xor_sync(0xffffffffu, mx0, 1));
            mx0 = fmaxf(mx0, __shfl_xor_sync(0xffffffffu, mx0, 2));
            mx1 = fmaxf(mx1, __shfl_xor_sync(0xffffffffu, mx1, 1));
            mx1 = fmaxf(mx1, __shfl_xor_sync(0xffffffffu, mx1, 2));
            const float mn0 = fmaxf(mr[mfr][0], mx0), mn1 = fmaxf(mr[mfr][1], mx1);
            const float a0 = ex2f(mr[mfr][0] - mn0), a1 = ex2f(mr[mfr][1] - mn1);

            #pragma unroll
            for (int nt = 0; nt < 8; nt++) {
                pl[mfr][nt] = h2ex2(pack_h2(sc[mfr][nt][0] - mn0, sc[mfr][nt][1] - mn0));
                ph[mfr][nt] = h2ex2(pack_h2(sc[mfr][nt][2] - mn1, sc[mfr][nt][3] - mn1));
            }

            float sacc[4] = {0.f, 0.f, 0.f, 0.f};
            #pragma unroll
            for (int ks = 0; ks < 4; ks++)
                mma_f16(sacc, pl[mfr][2*ks], ph[mfr][2*ks], pl[mfr][2*ks+1], ph[mfr][2*ks+1], ONES_H2, ONES_H2);

            lr[mfr][0] = lr[mfr][0]*a0 + sacc[0];
            lr[mfr][1] = lr[mfr][1]*a1 + sacc[2];
            mr[mfr][0] = mn0; mr[mfr][1] = mn1;
            #pragma unroll
            for (int nt = 0; nt < 8; nt++) {
                O[mfr][nt][0] *= a0; O[mfr][nt][1] *= a0;
                O[mfr][nt][2] *= a1; O[mfr][nt][3] *= a1;
            }
        }

        #pragma unroll
        for (int ks = 0; ks < 4; ks++) {
            const int e = 2*ks, o = 2*ks + 1;
            #pragma unroll
            for (int dg = 0; dg < 4; dg++) {
                uint32_t vf[4];
                uint32_t off = SWZ128((uint32_t)(((ks*16 + rloc) << 7) + dg*32 + kpiece));
                ldsm_x4_t(vf[0], vf[1], vf[2], vf[3], vb + off);
                #pragma unroll
                for (int mfr = 0; mfr < 2; mfr++) {
                    mma_f16(O[mfr][dg*2],   pl[mfr][e], ph[mfr][e], pl[mfr][o], ph[mfr][o], vf[0], vf[1]);
                    mma_f16(O[mfr][dg*2+1], pl[mfr][e], ph[mfr][e], pl[mfr][o], ph[mfr][o], vf[2], vf[3]);
                }
            }
        }
    }

    const int qr = lane >> 2;
    const int qc = (lane & 3) * 2;
    #pragma unroll
    for (int mfr = 0; mfr < 2; mfr++) {
        const float i0 = 1.f / lr[mfr][0], i1 = 1.f / lr[mfr][1];
        const int rowA = q0 + wid*32 + mfr*16 + qr;
        #pragma unroll
        for (int nt = 0; nt < 8; nt++) {
            float v0 = O[mfr][nt][0]*i0, v1 = O[mfr][nt][1]*i0;
            float v2 = O[mfr][nt][2]*i1, v3 = O[mfr][nt][3]*i1;
            size_t oA = rbase + (size_t)rowA*D_MODEL + nt*8 + qc;
            size_t oB = oA + 8*D_MODEL;
            *(uint32_t*)(ctx16 + oA) = pack_h2(v0, v1);
            *(uint32_t*)(ctx16 + oB) = pack_h2(v2, v3);
        }
    }
}

// ================= residual add + LayerNorm (float4 vectorized) ============
template<bool EMIT16>
__global__ __launch_bounds__(256)
void add_ln_kernel(const float* __restrict__ A, const float* __restrict__ Bm,
                   const float* __restrict__ gamma, const float* __restrict__ beta,
                   float* __restrict__ out, __half* __restrict__ o16)
{
    __shared__ float sh[8];
    const int row = blockIdx.x;
    const int tid = threadIdx.x;
    const int c   = tid * 4;
    const float* a  = A  + (size_t)row*D_MODEL;
    const float* bb = Bm + (size_t)row*D_MODEL;
    float4 va = *(const float4*)(a + c);
    float4 vb = *(const float4*)(bb + c);
    float v[4] = {va.x+vb.x, va.y+vb.y, va.z+vb.z, va.w+vb.w};
    float s = v[0]+v[1]+v[2]+v[3];
    #pragma unroll
    for (int o = 16; o; o >>= 1) s += __shfl_xor_sync(0xffffffffu, s, o);
    if ((tid & 31) == 0) sh[tid >> 5] = s;
    __syncthreads();
    float tot = 0.f;
    #pragma unroll
    for (int i = 0; i < 8; i++) tot += sh[i];
    const float mean = tot * (1.f/(float)D_MODEL);
    float s2 = 0.f;
    #pragma unroll
    for (int i = 0; i < 4; i++) { float d = v[i]-mean; s2 += d*d; }
    #pragma unroll
    for (int o = 16; o; o >>= 1) s2 += __shfl_xor_sync(0xffffffffu, s2, o);
    __syncthreads();
    if ((tid & 31) == 0) sh[tid >> 5] = s2;
    __syncthreads();
    float tot2 = 0.f;
    #pragma unroll
    for (int i = 0; i < 8; i++) tot2 += sh[i];
    const float inv = 1.f / (sqrtf(tot2 * (1.f/(float)D_MODEL)) + LN_EPS);
    float4 vg = *(const float4*)(gamma + c);
    float4 ve = *(const float4*)(beta + c);
    float r0 = vg.x*(v[0]-mean)*inv + ve.x;
    float r1 = vg.y*(v[1]-mean)*inv + ve.y;
    float r2 = vg.z*(v[2]-mean)*inv + ve.z;
    float r3 = vg.w*(v[3]-mean)*inv + ve.w;
    *(float4*)(out + (size_t)row*D_MODEL + c) = make_float4(r0, r1, r2, r3);
    if (EMIT16) {
        uint2 o2;
        o2.x = pack_h2(r0, r1);
        o2.y = pack_h2(r2, r3);
        *(uint2*)(o16 + (size_t)row*D_MODEL + c) = o2;
    }
}

// ================= launcher =================
extern "C" void kernel_launch(void* const* d_in, const int* in_sizes, int n_in,
                              void* d_out, int out_size)
{
    const float* x   = (const float*)d_in[0];
    const float* Wq  = (const float*)d_in[1];
    const float* bq  = (const float*)d_in[2];
    const float* Wk  = (const float*)d_in[3];
    const float* bk  = (const float*)d_in[4];
    const float* Wv  = (const float*)d_in[5];
    const float* bv  = (const float*)d_in[6];
    const float* Wo  = (const float*)d_in[7];
    const float* bo  = (const float*)d_in[8];
    const float* W1  = (const float*)d_in[9];
    const float* b1  = (const float*)d_in[10];
    const float* W2  = (const float*)d_in[11];
    const float* b2  = (const float*)d_in[12];
    const float* g1  = (const float*)d_in[13];
    const float* be1 = (const float*)d_in[14];
    const float* g2  = (const float*)d_in[15];
    const float* be2 = (const float*)d_in[16];
    float* out = (float*)d_out;

    float *t1,*h;
    __half *x16,*q16,*k16,*v16,*c16,*h16,*f116,*wqkv16,*wo16,*w116,*w216;
    cudaGetSymbolAddress((void**)&t1,     g_t1);
    cudaGetSymbolAddress((void**)&h,      g_h);
    cudaGetSymbolAddress((void**)&x16,    g_x16);
    cudaGetSymbolAddress((void**)&q16,    g_q16);
    cudaGetSymbolAddress((void**)&k16,    g_k16);
    cudaGetSymbolAddress((void**)&v16,    g_v16);
    cudaGetSymbolAddress((void**)&c16,    g_c16);
    cudaGetSymbolAddress((void**)&h16,    g_h16);
    cudaGetSymbolAddress((void**)&f116,   g_f116);
    cudaGetSymbolAddress((void**)&wqkv16, g_wqkv16);
    cudaGetSymbolAddress((void**)&wo16,   g_wo16);
    cudaGetSymbolAddress((void**)&w116,   g_w116);
    cudaGetSymbolAddress((void**)&w216,   g_w216);

    cudaFuncSetAttribute(gemm_mma<0>, cudaFuncAttributeMaxDynamicSharedMemorySize, GEMM_SMEM);
    cudaFuncSetAttribute(gemm_mma<1>, cudaFuncAttributeMaxDynamicSharedMemorySize, GEMM_SMEM);
    cudaFuncSetAttribute(gemm_mma<3>, cudaFuncAttributeMaxDynamicSharedMemorySize, GEMM_SMEM);
    cudaFuncSetAttribute(attention_mma, cudaFuncAttributeMaxDynamicSharedMemorySize, ATT_SMEM);

    const int nX = NROWS*D_MODEL;
    dim3 thr(128);

    cvt_f16_kernel<<<nX/4096, 256>>>(x, x16, nX);
    transpose_all_kernel<<<3072, 256>>>(Wq, Wk, Wv, Wo, W1, W2,
                                        wqkv16, wo16, w116, w216);
    // fused QKV (Q prescaled fp16, K/V fp16)
    gemm_mma<3><<<dim3(24, 32), thr, GEMM_SMEM>>>(x16, wqkv16, bq, bk, bv,
                                                  nullptr, q16, k16, v16, D_MODEL, D_MODEL);
    // attention (4 warps x 32 rows)
    attention_mma<<<dim3(SEQ/128, BATCH*NHEADS), thr, ATT_SMEM>>>(q16, k16, v16, c16);
    // Wo -> t1 (f32)
    gemm_mma<0><<<dim3(8, 32), thr, GEMM_SMEM>>>(c16, wo16, bo, nullptr, nullptr,
                                                 t1, nullptr, nullptr, nullptr, D_MODEL, D_MODEL);
    // LN1 -> h (f32) + h16
    add_ln_kernel<true><<<NROWS, 256>>>(x, t1, g1, be1, h, h16);
    // FF1 (relu -> fp16)
    gemm_mma<1><<<dim3(32, 32), thr, GEMM_SMEM>>>(h16, w116, b1, nullptr, nullptr,
                                                  nullptr, f116, nullptr, nullptr, D_MODEL, D_FF);
    // FF2 -> t1 (f32)
    gemm_mma<0><<<dim3(8, 32), thr, GEMM_SMEM>>>(f116, w216, b2, nullptr, nullptr,
                                                 t1, nullptr, nullptr, nullptr, D_FF, D_MODEL);
    // LN2 -> out
    add_ln_kernel<false><<<NROWS, 256>>>(h, t1, g2, be2, out, nullptr);
}